// round 6
// baseline (speedup 1.0000x reference)
#include <cuda_runtime.h>
#include <cuda_fp16.h>
#include <math.h>
#include <stdint.h>

// Problem constants (fixed by the dataset)
#define NN   50000
#define NE   1600000
#define DIN  128
#define DHID 128
#define DOUT 64
#define DFCH 256

// ---------------- scratch (device globals; no allocation allowed) ----------
static __device__ __align__(16) __half g_H1h[NN * DHID];  // x @ W1, fp16
static __device__ __align__(16) __half g_A1h[NN * DHID];  // relu(agg1 + b1), fp16
static __device__ __align__(16) __half g_H2h[NN * DOUT];  // A1 @ W2, fp16
static __device__ __align__(16) __half g_F1h[NN * DFCH];  // relu(x@Wf1+bf1), fp16
static __device__ __align__(16) __half g_FCh[NN * DOUT];  // F1@Wf2+bf2, fp16
static __device__ __align__(16) __half g_Zh[NN * DOUT];   // 0.5*gcn + 0.5*fc, fp16
static __device__ int   g_cnt[NN];                        // zero at rest (restored each run)
static __device__ int   g_rowptr[NN + 1];
static __device__ int   g_cursor[NN];
static __device__ int   g_col[NE];
static __device__ float g_dinv[NN];
static __device__ int   g_bsum[256];
static __device__ int   g_tick;                           // zero at rest

// ---------------- scan kernels ----------------------------------------------
// per-block reduce of counts; last block also scans the block sums (fused scanb)
__global__ void reduce2_k(int nbl, int n) {
    __shared__ int sm[256];
    __shared__ int lastBlk;
    int t = threadIdx.x;
    int i = blockIdx.x * 256 + t;
    sm[t] = (i < n) ? g_cnt[i] : 0;
    __syncthreads();
    for (int d = 128; d > 0; d >>= 1) {
        if (t < d) sm[t] += sm[t + d];
        __syncthreads();
    }
    if (t == 0) {
        g_bsum[blockIdx.x] = sm[0];
        __threadfence();
        lastBlk = (atomicAdd(&g_tick, 1) == nbl - 1);
    }
    __syncthreads();
    if (lastBlk) {
        __threadfence();
        int v = (t < nbl) ? g_bsum[t] : 0;
        sm[t] = v;
        __syncthreads();
        for (int d = 1; d < 256; d <<= 1) {
            int a = (t >= d) ? sm[t - d] : 0;
            __syncthreads();
            sm[t] += a;
            __syncthreads();
        }
        if (t < nbl) g_bsum[t] = sm[t] - v;
        if (t == 0) { g_rowptr[n] = sm[255]; g_tick = 0; }
    }
}

// local exclusive scan + block offset; also dinv; re-zeroes g_cnt for next run
__global__ void scane_k(int n) {
    __shared__ int sm[256];
    int t = threadIdx.x;
    int i = blockIdx.x * 256 + t;
    int v = (i < n) ? g_cnt[i] : 0;
    sm[t] = v;
    __syncthreads();
    for (int d = 1; d < 256; d <<= 1) {
        int a = (t >= d) ? sm[t - d] : 0;
        __syncthreads();
        sm[t] += a;
        __syncthreads();
    }
    if (i < n) {
        int excl = g_bsum[blockIdx.x] + sm[t] - v;
        g_rowptr[i] = excl;
        g_cursor[i] = excl;
        g_dinv[i]   = rsqrtf((float)(v + 1));
        g_cnt[i]    = 0;                       // restore zeroed state (no memset needed)
    }
}

// ---------------- TF32 helpers ---------------------------------------------
__device__ __forceinline__ float f2tf32(float f) {
    uint32_t u;
    asm("cvt.rna.tf32.f32 %0, %1;" : "=r"(u) : "f"(f));
    return __uint_as_float(u);
}

__device__ __forceinline__ void mma_tf32(float* d, const uint32_t* a, const uint32_t* b) {
    asm volatile(
        "mma.sync.aligned.m16n8k8.row.col.f32.tf32.tf32.f32 "
        "{%0,%1,%2,%3}, {%4,%5,%6,%7}, {%8,%9}, {%0,%1,%2,%3};"
        : "+f"(d[0]), "+f"(d[1]), "+f"(d[2]), "+f"(d[3])
        : "r"(a[0]), "r"(a[1]), "r"(a[2]), "r"(a[3]), "r"(b[0]), "r"(b[1]));
}

// ---------------- TF32 tensor-core GEMM body --------------------------------
template <int K, int N, int BN, bool BIAS, bool RELU, bool A_HALF, bool HALF_OUT>
__device__ __forceinline__ void gemm_body(const void* Av, const float* __restrict__ W,
                                          const float* __restrict__ bias,
                                          void* __restrict__ Cv, int nRows,
                                          int tileM, int colBlk,
                                          float* As, float* Ws) {
    constexpr int BM = 128, BK = 32;
    constexpr int AS_STRIDE = BK + 4;              // 36: bank = lane for a-frags
    constexpr int WS_STRIDE = BN + 8;              // mod 32 == 8: conflict-free b-frags
    constexpr int NT = BN / 16;

    const int tid = threadIdx.x;
    const int lane = tid & 31;
    const int wid = tid >> 5;
    const int warpM = wid & 3;
    const int warpN = wid >> 2;
    const int rowBase = tileM * BM;
    const int colBase = colBlk * BN;

    float acc[2][NT][4];
#pragma unroll
    for (int mt = 0; mt < 2; mt++)
#pragma unroll
        for (int nt = 0; nt < NT; nt++)
#pragma unroll
            for (int i = 0; i < 4; i++) acc[mt][nt][i] = 0.f;

    for (int k0 = 0; k0 < K; k0 += BK) {
#pragma unroll
        for (int i = 0; i < 4; i++) {
            int s = tid + i * 256;
            int m = s >> 3;
            int c4 = (s & 7) * 4;
            float4 v = make_float4(0.f, 0.f, 0.f, 0.f);
            int grow = rowBase + m;
            if (grow < nRows) {
                if (A_HALF) {
                    const __half* Ah = (const __half*)Av;
                    uint2 u = *(const uint2*)&Ah[(size_t)grow * K + k0 + c4];
                    float2 p0 = __half22float2(*(const __half2*)&u.x);
                    float2 p1 = __half22float2(*(const __half2*)&u.y);
                    v = make_float4(p0.x, p0.y, p1.x, p1.y);
                } else {
                    const float* Af = (const float*)Av;
                    v = *(const float4*)&Af[(size_t)grow * K + k0 + c4];
                }
            }
            float* p = &As[m * AS_STRIDE + c4];
            p[0] = f2tf32(v.x); p[1] = f2tf32(v.y);
            p[2] = f2tf32(v.z); p[3] = f2tf32(v.w);
        }
#pragma unroll
        for (int i = 0; i < BN / 32; i++) {
            int s = tid + i * 256;
            int r = s / (BN / 4);
            int c4 = (s % (BN / 4)) * 4;
            float4 v = *(const float4*)&W[(size_t)(k0 + r) * N + colBase + c4];
            float* p = &Ws[r * WS_STRIDE + c4];
            p[0] = f2tf32(v.x); p[1] = f2tf32(v.y);
            p[2] = f2tf32(v.z); p[3] = f2tf32(v.w);
        }
        __syncthreads();

#pragma unroll
        for (int ks = 0; ks < BK / 8; ks++) {
            const int k8 = ks * 8;
            uint32_t a[2][4];
#pragma unroll
            for (int mt = 0; mt < 2; mt++) {
                const float* Ap = &As[(warpM * 32 + mt * 16 + (lane >> 2)) * AS_STRIDE
                                      + k8 + (lane & 3)];
                a[mt][0] = __float_as_uint(Ap[0]);
                a[mt][1] = __float_as_uint(Ap[8 * AS_STRIDE]);
                a[mt][2] = __float_as_uint(Ap[4]);
                a[mt][3] = __float_as_uint(Ap[8 * AS_STRIDE + 4]);
            }
#pragma unroll
            for (int nt = 0; nt < NT; nt++) {
                const int n0 = warpN * (NT * 8) + nt * 8 + (lane >> 2);
                uint32_t b[2];
                b[0] = __float_as_uint(Ws[(k8 + (lane & 3)) * WS_STRIDE + n0]);
                b[1] = __float_as_uint(Ws[(k8 + (lane & 3) + 4) * WS_STRIDE + n0]);
                mma_tf32(acc[0][nt], a[0], b);
                mma_tf32(acc[1][nt], a[1], b);
            }
        }
        __syncthreads();
    }

#pragma unroll
    for (int mt = 0; mt < 2; mt++) {
#pragma unroll
        for (int half = 0; half < 2; half++) {
            int row = rowBase + warpM * 32 + mt * 16 + (lane >> 2) + half * 8;
            if (row >= nRows) continue;
#pragma unroll
            for (int nt = 0; nt < NT; nt++) {
                int col = colBase + warpN * (NT * 8) + nt * 8 + (lane & 3) * 2;
                float v0 = acc[mt][nt][half * 2 + 0];
                float v1 = acc[mt][nt][half * 2 + 1];
                if (BIAS) { v0 += bias[col]; v1 += bias[col + 1]; }
                if (RELU) { v0 = fmaxf(v0, 0.f); v1 = fmaxf(v1, 0.f); }
                if (HALF_OUT) {
                    __half* C = (__half*)Cv;
                    *(__half2*)&C[(size_t)row * N + col] = __floats2half2_rn(v0, v1);
                } else {
                    float* C = (float*)Cv;
                    *(float2*)&C[(size_t)row * N + col] = make_float2(v0, v1);
                }
            }
        }
    }
}

// ---------------- aggregation node body (fp16 gathers, one warp/node) -------
// COMBINE: out = 0.5*(di*acc + bias) + 0.5*FC[row]; else optional RELU.
template <int F, bool RELU, bool COMBINE>
__device__ __forceinline__ void agg_node(int gw, const __half* __restrict__ H,
                                         const float* __restrict__ bias,
                                         const __half* __restrict__ FCh,
                                         __half* __restrict__ Out) {
    const int lane = threadIdx.x & 31;
    constexpr int FPT = F / 32;        // 4 or 2
    const int colb = lane * FPT;
    const float di = g_dinv[gw];

    float acc[FPT];
    if constexpr (FPT == 4) {
        uint2 u = *(const uint2*)&H[(size_t)gw * F + colb];
        float2 p0 = __half22float2(*(const __half2*)&u.x);
        float2 p1 = __half22float2(*(const __half2*)&u.y);
        acc[0] = di * p0.x; acc[1] = di * p0.y;
        acc[2] = di * p1.x; acc[3] = di * p1.y;
    } else {
        uint32_t u = *(const uint32_t*)&H[(size_t)gw * F + colb];
        float2 p = __half22float2(*(const __half2*)&u);
        acc[0] = di * p.x; acc[1] = di * p.y;
    }

    int e = g_rowptr[gw];
    const int end = g_rowptr[gw + 1];
    for (; e + 1 < end; e += 2) {
        int s0 = __ldg(&g_col[e]);
        int s1 = __ldg(&g_col[e + 1]);
        float d0 = __ldg(&g_dinv[s0]);
        float d1 = __ldg(&g_dinv[s1]);
        if constexpr (FPT == 4) {
            uint2 u0 = *(const uint2*)&H[(size_t)s0 * F + colb];
            uint2 u1 = *(const uint2*)&H[(size_t)s1 * F + colb];
            float2 a0 = __half22float2(*(const __half2*)&u0.x);
            float2 a1 = __half22float2(*(const __half2*)&u0.y);
            float2 b0 = __half22float2(*(const __half2*)&u1.x);
            float2 b1 = __half22float2(*(const __half2*)&u1.y);
            acc[0] += d0 * a0.x + d1 * b0.x;
            acc[1] += d0 * a0.y + d1 * b0.y;
            acc[2] += d0 * a1.x + d1 * b1.x;
            acc[3] += d0 * a1.y + d1 * b1.y;
        } else {
            uint32_t u0 = *(const uint32_t*)&H[(size_t)s0 * F + colb];
            uint32_t u1 = *(const uint32_t*)&H[(size_t)s1 * F + colb];
            float2 a = __half22float2(*(const __half2*)&u0);
            float2 b = __half22float2(*(const __half2*)&u1);
            acc[0] += d0 * a.x + d1 * b.x;
            acc[1] += d0 * a.y + d1 * b.y;
        }
    }
    if (e < end) {
        int s0 = __ldg(&g_col[e]);
        float d0 = __ldg(&g_dinv[s0]);
        if constexpr (FPT == 4) {
            uint2 u0 = *(const uint2*)&H[(size_t)s0 * F + colb];
            float2 a0 = __half22float2(*(const __half2*)&u0.x);
            float2 a1 = __half22float2(*(const __half2*)&u0.y);
            acc[0] += d0 * a0.x; acc[1] += d0 * a0.y;
            acc[2] += d0 * a1.x; acc[3] += d0 * a1.y;
        } else {
            uint32_t u0 = *(const uint32_t*)&H[(size_t)s0 * F + colb];
            float2 a = __half22float2(*(const __half2*)&u0);
            acc[0] += d0 * a.x; acc[1] += d0 * a.y;
        }
    }

    float fc[FPT];
    if constexpr (COMBINE) {
        if constexpr (FPT == 2) {
            float2 f = __half22float2(*(const __half2*)&FCh[(size_t)gw * F + colb]);
            fc[0] = f.x; fc[1] = f.y;
        } else {
            uint2 u = *(const uint2*)&FCh[(size_t)gw * F + colb];
            float2 f0 = __half22float2(*(const __half2*)&u.x);
            float2 f1 = __half22float2(*(const __half2*)&u.y);
            fc[0] = f0.x; fc[1] = f0.y; fc[2] = f1.x; fc[3] = f1.y;
        }
    }

#pragma unroll
    for (int j = 0; j < FPT; j++) {
        float o = di * acc[j] + bias[colb + j];
        if (RELU) o = fmaxf(o, 0.f);
        if (COMBINE) o = 0.5f * o + 0.5f * fc[j];
        acc[j] = o;
    }
    if constexpr (FPT == 4) {
        uint2 u;
        *(__half2*)&u.x = __floats2half2_rn(acc[0], acc[1]);
        *(__half2*)&u.y = __floats2half2_rn(acc[2], acc[3]);
        *(uint2*)&Out[(size_t)gw * F + colb] = u;
    } else {
        *(__half2*)&Out[(size_t)gw * F + colb] = __floats2half2_rn(acc[0], acc[1]);
    }
}

// ---- fused: H1 GEMM tiles (even blocks) || histogram chunks (odd blocks) ---
__global__ void __launch_bounds__(256, 2) h1hist_k(const float* __restrict__ x,
                                                   const float* __restrict__ W1,
                                                   __half* __restrict__ H1,
                                                   const int* __restrict__ dst,
                                                   int ne, int mb, int n) {
    const int role = blockIdx.x & 1;
    const int slot = blockIdx.x >> 1;
    if (role == 1) {                               // histogram chunk
        const int nch = gridDim.x >> 1;
        const int per = (ne + nch - 1) / nch;
        const int s = slot * per;
        const int e = min(s + per, ne);
        for (int i = s + (int)threadIdx.x; i < e; i += 256)
            atomicAdd(&g_cnt[dst[i]], 1);
        return;
    }
    if (slot >= mb) return;
    __shared__ float As[128 * 36];
    __shared__ float Ws[32 * 136];
    gemm_body<DIN, DHID, 128, false, false, false, true>(
        x, W1, nullptr, H1, n, slot, 0, As, Ws);
}

// ---- fused: F1 GEMM tiles (3 of 4 blocks) || CSR-fill chunks (1 of 4) ------
__global__ void __launch_bounds__(256, 2) f1fill_k(const float* __restrict__ x,
                                                   const float* __restrict__ Wf1,
                                                   const float* __restrict__ bf1,
                                                   __half* __restrict__ F1,
                                                   const int* __restrict__ ei,
                                                   int ne, int mb, int n) {
    const int role = blockIdx.x & 3;
    const int grp  = blockIdx.x >> 2;
    if (role == 3) {                               // fill chunk
        const int nch = gridDim.x >> 2;
        const int per = (ne + nch - 1) / nch;
        const int s = grp * per;
        const int e = min(s + per, ne);
        for (int i = s + (int)threadIdx.x; i < e; i += 256) {
            int sv = ei[i];
            int dv = ei[ne + i];
            g_col[atomicAdd(&g_cursor[dv], 1)] = sv;
        }
        return;
    }
    const int idx = grp * 3 + role;
    if (idx >= 2 * mb) return;
    __shared__ float As[128 * 36];
    __shared__ float Ws[32 * 136];
    gemm_body<DIN, DFCH, 128, true, true, false, true>(
        x, Wf1, bf1, F1, n, idx % mb, idx / mb, As, Ws);
}

// ---- fused: agg1 (15 of 16 blocks) || FC GEMM tiles (1 of 16) --------------
__global__ void __launch_bounds__(256) aggfc_k(const __half* __restrict__ H1,
                                               const float* __restrict__ b1,
                                               __half* __restrict__ A1,
                                               const __half* __restrict__ F1,
                                               const float* __restrict__ Wf2,
                                               const float* __restrict__ bf2,
                                               __half* __restrict__ FC,
                                               int n, int mb) {
    __shared__ float smem[128 * 36 + 32 * 72];
    const int local = blockIdx.x & 15;
    const int grp = blockIdx.x >> 4;
    if (local == 15) {                             // FC GEMM tile
        if (grp >= mb) return;
        gemm_body<DFCH, DOUT, 64, true, false, true, true>(
            F1, Wf2, bf2, FC, n, grp, 0, smem, smem + 128 * 36);
        return;
    }
    const int aggIdx = grp * 15 + local;           // 8 node-warps per block
    const int gw = aggIdx * 8 + ((int)threadIdx.x >> 5);
    if (gw >= n) return;
    agg_node<DHID, true, false>(gw, H1, b1, nullptr, A1);
}

// ---- plain GEMM (fp16 A): H2 = A1 @ W2 -------------------------------------
__global__ void __launch_bounds__(256, 2) gemmh2_k(const __half* __restrict__ A1,
                                                   const float* __restrict__ W2,
                                                   __half* __restrict__ H2, int n) {
    __shared__ float As[128 * 36];
    __shared__ float Ws[32 * 72];
    gemm_body<DHID, DOUT, 64, false, false, true, true>(
        A1, W2, nullptr, H2, n, blockIdx.x, 0, As, Ws);
}

// ---- agg2 + combine: z = 0.5*(agg(H2)+b2) + 0.5*FC -------------------------
__global__ void __launch_bounds__(256) agg2z_k(const __half* __restrict__ H2,
                                               const float* __restrict__ b2,
                                               const __half* __restrict__ FC,
                                               __half* __restrict__ Z, int n) {
    const int gw = (blockIdx.x * 256 + threadIdx.x) >> 5;
    if (gw >= n) return;
    agg_node<DOUT, false, true>(gw, H2, b2, FC, Z);
}

// ---------------- decode (fp16 z): out[q] = dot(z[a], z[b]) -----------------
__global__ void __launch_bounds__(256) decodeh_k(const int* __restrict__ eli,
                                                 const __half* __restrict__ zh,
                                                 float* __restrict__ out, int nq) {
    int t = blockIdx.x * 256 + threadIdx.x;
    int q = t >> 4;
    int l = t & 15;
    if (q >= nq) return;
    int a = eli[q];
    int b = eli[nq + q];
    uint2 ua = *(const uint2*)&zh[(size_t)a * DOUT + l * 4];
    uint2 ub = *(const uint2*)&zh[(size_t)b * DOUT + l * 4];
    float2 a0 = __half22float2(*(const __half2*)&ua.x);
    float2 a1 = __half22float2(*(const __half2*)&ua.y);
    float2 b0 = __half22float2(*(const __half2*)&ub.x);
    float2 b1 = __half22float2(*(const __half2*)&ub.y);
    float p = a0.x * b0.x + a0.y * b0.y + a1.x * b1.x + a1.y * b1.y;
    p += __shfl_xor_sync(0xffffffffu, p, 8);
    p += __shfl_xor_sync(0xffffffffu, p, 4);
    p += __shfl_xor_sync(0xffffffffu, p, 2);
    p += __shfl_xor_sync(0xffffffffu, p, 1);
    if (l == 0) out[q] = p;
}

// ---------------- launch ----------------------------------------------------
extern "C" void kernel_launch(void* const* d_in, const int* in_sizes, int n_in,
                              void* d_out, int out_size) {
    const float* x   = (const float*)d_in[0];
    const int*   ei  = (const int*)d_in[1];
    const int*   eli = (const int*)d_in[2];
    const float* W1  = (const float*)d_in[3];
    const float* b1  = (const float*)d_in[4];
    const float* W2  = (const float*)d_in[5];
    const float* b2  = (const float*)d_in[6];
    const float* Wf1 = (const float*)d_in[7];
    const float* bf1 = (const float*)d_in[8];
    const float* Wf2 = (const float*)d_in[9];
    const float* bf2 = (const float*)d_in[10];
    float* out = (float*)d_out;

    const int n  = in_sizes[0] / DIN;
    const int ne = in_sizes[1] / 2;
    const int nq = in_sizes[2] / 2;

    __half *pH1h, *pA1h, *pH2h, *pF1h, *pFCh, *pZh;
    cudaGetSymbolAddress((void**)&pH1h, g_H1h);
    cudaGetSymbolAddress((void**)&pA1h, g_A1h);
    cudaGetSymbolAddress((void**)&pH2h, g_H2h);
    cudaGetSymbolAddress((void**)&pF1h, g_F1h);
    cudaGetSymbolAddress((void**)&pFCh, g_FCh);
    cudaGetSymbolAddress((void**)&pZh,  g_Zh);

    const int mb = (n + 127) / 128;                 // GEMM row tiles
    const int nb = (n + 255) / 256;                 // scan blocks
    const int aggBlocks = (n * 32 + 255) / 256;     // warp-per-node blocks (8 nodes/blk)

    // 1. [H1 GEMM || histogram] (g_cnt arrives zeroed from previous run / load)
    h1hist_k<<<2 * mb, 256>>>(x, W1, pH1h, ei + ne, ne, mb, n);
    // 2. rowptr scan (reduce + block-sum scan fused; then local scan + cnt reset)
    reduce2_k<<<nb, 256>>>(nb, n);
    scane_k<<<nb, 256>>>(n);
    // 3. [F1 GEMM || CSR fill]
    const int ngrp = (2 * mb + 2) / 3;
    f1fill_k<<<4 * ngrp, 256>>>(x, Wf1, bf1, pF1h, ei, ne, mb, n);
    // 4. [agg1 -> A1 || FC GEMM -> FC]
    const int agrp = (aggBlocks + 14) / 15;
    aggfc_k<<<16 * agrp, 256>>>(pH1h, b1, pA1h, pF1h, Wf2, bf2, pFCh, n, mb);
    // 5. H2 = A1 @ W2
    gemmh2_k<<<mb, 256>>>(pA1h, W2, pH2h, n);
    // 6. z = 0.5*(agg(H2)+b2) + 0.5*FC
    agg2z_k<<<aggBlocks, 256>>>(pH2h, b2, pFCh, pZh, n);
    // 7. edge dot-product decode
    decodeh_k<<<(nq * 16 + 255) / 256, 256>>>(eli, pZh, out, nq);
}

// round 8
// speedup vs baseline: 1.0194x; 1.0194x over previous
#include <cuda_runtime.h>
#include <cuda_fp16.h>
#include <math.h>
#include <stdint.h>

// Problem constants (fixed by the dataset)
#define NN   50000
#define NE   1600000
#define DIN  128
#define DHID 128
#define DOUT 64
#define DFCH 256

// ---------------- scratch (device globals; no allocation allowed) ----------
static __device__ __align__(16) __half g_H1h[NN * DHID];  // x @ W1, fp16
static __device__ __align__(16) __half g_A1h[NN * DHID];  // relu(agg1 + b1), fp16
static __device__ __align__(16) __half g_H2h[NN * DOUT];  // A1 @ W2, fp16
static __device__ __align__(16) __half g_F1h[NN * DFCH];  // relu(x@Wf1+bf1), fp16
static __device__ __align__(16) __half g_FCh[NN * DOUT];  // F1@Wf2+bf2, fp16
static __device__ __align__(16) __half g_Zh[NN * DOUT];   // 0.5*gcn + 0.5*fc, fp16
// tf32-pre-rounded weights
static __device__ __align__(16) float g_W1r [DIN * DHID];
static __device__ __align__(16) float g_Wf1r[DIN * DFCH];
static __device__ __align__(16) float g_W2r [DHID * DOUT];
static __device__ __align__(16) float g_Wf2r[DFCH * DOUT];
static __device__ int   g_cnt[NN];                        // zero at rest
static __device__ int   g_rowptr[NN + 1];
static __device__ int   g_cursor[NN];
static __device__ int   g_col[NE];
static __device__ float g_dinv[NN];
static __device__ int   g_bsum[256];
static __device__ int   g_tick;                           // zero at rest

// ---------------- TF32 round helper -----------------------------------------
__device__ __forceinline__ float f2tf32(float f) {
    uint32_t u;
    asm("cvt.rna.tf32.f32 %0, %1;" : "=r"(u) : "f"(f));
    return __uint_as_float(u);
}

// ---------------- weight pre-round kernel ------------------------------------
__global__ void prep_k(const float* __restrict__ W1, const float* __restrict__ Wf1,
                       const float* __restrict__ W2, const float* __restrict__ Wf2) {
    int i = blockIdx.x * 256 + threadIdx.x;
    if (i < DIN * DHID)  g_W1r[i]  = f2tf32(W1[i]);
    if (i < DIN * DFCH)  g_Wf1r[i] = f2tf32(Wf1[i]);
    if (i < DHID * DOUT) g_W2r[i]  = f2tf32(W2[i]);
    if (i < DFCH * DOUT) g_Wf2r[i] = f2tf32(Wf2[i]);
}

// ---------------- scan kernels ----------------------------------------------
__global__ void reduce2_k(int nbl, int n) {
    __shared__ int sm[256];
    __shared__ int lastBlk;
    int t = threadIdx.x;
    int i = blockIdx.x * 256 + t;
    sm[t] = (i < n) ? g_cnt[i] : 0;
    __syncthreads();
    for (int d = 128; d > 0; d >>= 1) {
        if (t < d) sm[t] += sm[t + d];
        __syncthreads();
    }
    if (t == 0) {
        g_bsum[blockIdx.x] = sm[0];
        __threadfence();
        lastBlk = (atomicAdd(&g_tick, 1) == nbl - 1);
    }
    __syncthreads();
    if (lastBlk) {
        __threadfence();
        int v = (t < nbl) ? g_bsum[t] : 0;
        sm[t] = v;
        __syncthreads();
        for (int d = 1; d < 256; d <<= 1) {
            int a = (t >= d) ? sm[t - d] : 0;
            __syncthreads();
            sm[t] += a;
            __syncthreads();
        }
        if (t < nbl) g_bsum[t] = sm[t] - v;
        if (t == 0) { g_rowptr[n] = sm[255]; g_tick = 0; }
    }
}

__global__ void scane_k(int n) {
    __shared__ int sm[256];
    int t = threadIdx.x;
    int i = blockIdx.x * 256 + t;
    int v = (i < n) ? g_cnt[i] : 0;
    sm[t] = v;
    __syncthreads();
    for (int d = 1; d < 256; d <<= 1) {
        int a = (t >= d) ? sm[t - d] : 0;
        __syncthreads();
        sm[t] += a;
        __syncthreads();
    }
    if (i < n) {
        int excl = g_bsum[blockIdx.x] + sm[t] - v;
        g_rowptr[i] = excl;
        g_cursor[i] = excl;
        g_dinv[i]   = rsqrtf((float)(v + 1));
        g_cnt[i]    = 0;                       // restore zeroed state
    }
}

// ---------------- mma / cp.async helpers ------------------------------------
__device__ __forceinline__ void mma_tf32(float* d, const uint32_t* a, const uint32_t* b) {
    asm volatile(
        "mma.sync.aligned.m16n8k8.row.col.f32.tf32.tf32.f32 "
        "{%0,%1,%2,%3}, {%4,%5,%6,%7}, {%8,%9}, {%0,%1,%2,%3};"
        : "+f"(d[0]), "+f"(d[1]), "+f"(d[2]), "+f"(d[3])
        : "r"(a[0]), "r"(a[1]), "r"(a[2]), "r"(a[3]), "r"(b[0]), "r"(b[1]));
}

__device__ __forceinline__ uint32_t smem_u32(const void* p) {
    return (uint32_t)__cvta_generic_to_shared(p);
}
__device__ __forceinline__ void cpa16(uint32_t dst, const void* src, int sz) {
    asm volatile("cp.async.cg.shared.global [%0], [%1], 16, %2;"
                 :: "r"(dst), "l"(src), "r"(sz));
}
__device__ __forceinline__ void cpa_commit() {
    asm volatile("cp.async.commit_group;");
}
template <int NP>
__device__ __forceinline__ void cpa_wait() {
    asm volatile("cp.async.wait_group %0;" :: "n"(NP));
}

// ------------ mma compute core over one (As, Ws) stage ----------------------
// As: BM x 32 (stride 36). Ws: 32 x BN (stride WS_STRIDE). acc[2][NT][4].
// CVT_A: apply round-to-nearest tf32 to a-fragments (A arrived raw fp32).
// W must always be pre-rounded.
template <int NT, int WS_STRIDE, bool CVT_A>
__device__ __forceinline__ void mma_stage(const float* As, const float* Ws,
                                          float acc[2][NT][4],
                                          int lane, int warpM, int warpN) {
#pragma unroll
    for (int ks = 0; ks < 4; ks++) {
        const int k8 = ks * 8;
        uint32_t a[2][4];
#pragma unroll
        for (int mt = 0; mt < 2; mt++) {
            const float* Ap = &As[(warpM * 32 + mt * 16 + (lane >> 2)) * 36
                                  + k8 + (lane & 3)];
            float v0 = Ap[0];
            float v1 = Ap[8 * 36];
            float v2 = Ap[4];
            float v3 = Ap[8 * 36 + 4];
            if (CVT_A) {
                v0 = f2tf32(v0); v1 = f2tf32(v1);
                v2 = f2tf32(v2); v3 = f2tf32(v3);
            }
            a[mt][0] = __float_as_uint(v0);
            a[mt][1] = __float_as_uint(v1);
            a[mt][2] = __float_as_uint(v2);
            a[mt][3] = __float_as_uint(v3);
        }
#pragma unroll
        for (int nt = 0; nt < NT; nt++) {
            const int n0 = warpN * (NT * 8) + nt * 8 + (lane >> 2);
            uint32_t b[2];
            b[0] = __float_as_uint(Ws[(k8 + (lane & 3)) * WS_STRIDE + n0]);
            b[1] = __float_as_uint(Ws[(k8 + (lane & 3) + 4) * WS_STRIDE + n0]);
            mma_tf32(acc[0][nt], a[0], b);
            mma_tf32(acc[1][nt], a[1], b);
        }
    }
}

// ------------ epilogue: bias/relu, fp16 store -------------------------------
template <int N, int NT, bool BIAS, bool RELU>
__device__ __forceinline__ void gemm_epi(float acc[2][NT][4],
                                         const float* __restrict__ bias,
                                         __half* __restrict__ C, int nRows,
                                         int rowBase, int colBase,
                                         int lane, int warpM, int warpN) {
#pragma unroll
    for (int mt = 0; mt < 2; mt++) {
#pragma unroll
        for (int half = 0; half < 2; half++) {
            int row = rowBase + warpM * 32 + mt * 16 + (lane >> 2) + half * 8;
            if (row >= nRows) continue;
#pragma unroll
            for (int nt = 0; nt < NT; nt++) {
                int col = colBase + warpN * (NT * 8) + nt * 8 + (lane & 3) * 2;
                float v0 = acc[mt][nt][half * 2 + 0];
                float v1 = acc[mt][nt][half * 2 + 1];
                if (BIAS) { v0 += bias[col]; v1 += bias[col + 1]; }
                if (RELU) { v0 = fmaxf(v0, 0.f); v1 = fmaxf(v1, 0.f); }
                *(__half2*)&C[(size_t)row * N + col] = __floats2half2_rn(v0, v1);
            }
        }
    }
}

// ------------ pipelined GEMM (fp32 A, K=128, BM=128, BN=128, cp.async) ------
// W must be tf32-pre-rounded; A rounded in registers at fragment load.
template <int N, bool BIAS, bool RELU>
__device__ __forceinline__ void gemm_pipe(const float* __restrict__ A,
                                          const float* __restrict__ W,
                                          const float* __restrict__ bias,
                                          __half* __restrict__ C, int nRows,
                                          int tileM, int colBlk, float* sm) {
    constexpr int K = 128, BN = 128, NT = 8;
    constexpr int ASZ = 128 * 36;        // floats per A stage
    constexpr int WSZ = 32 * 136;        // floats per W stage
    float* Asb[2] = {sm, sm + ASZ};
    float* Wsb[2] = {sm + 2 * ASZ, sm + 2 * ASZ + WSZ};

    const int tid = threadIdx.x;
    const int lane = tid & 31;
    const int wid = tid >> 5;
    const int warpM = wid & 3;
    const int warpN = wid >> 2;
    const int rowBase = tileM * 128;
    const int colBase = colBlk * BN;

    auto loadStage = [&](int st, int k0) {
#pragma unroll
        for (int i = 0; i < 4; i++) {
            int s = tid + i * 256;
            int m = s >> 3;
            int c4 = (s & 7) * 4;
            int grow = rowBase + m;
            int ok = grow < nRows;
            const float* src = &A[(size_t)(ok ? grow : 0) * K + k0 + c4];
            cpa16(smem_u32(&Asb[st][m * 36 + c4]), src, ok ? 16 : 0);
        }
#pragma unroll
        for (int i = 0; i < 4; i++) {
            int s = tid + i * 256;
            int r = s >> 5;
            int c4 = (s & 31) * 4;
            cpa16(smem_u32(&Wsb[st][r * 136 + c4]),
                  &W[(size_t)(k0 + r) * N + colBase + c4], 16);
        }
        cpa_commit();
    };

    float acc[2][NT][4];
#pragma unroll
    for (int mt = 0; mt < 2; mt++)
#pragma unroll
        for (int nt = 0; nt < NT; nt++)
#pragma unroll
            for (int i = 0; i < 4; i++) acc[mt][nt][i] = 0.f;

    loadStage(0, 0);
#pragma unroll
    for (int it = 0; it < 4; it++) {
        int st = it & 1;
        if (it < 3) loadStage(st ^ 1, (it + 1) * 32);
        if (it < 3) cpa_wait<1>(); else cpa_wait<0>();
        __syncthreads();
        mma_stage<NT, 136, true>(Asb[st], Wsb[st], acc, lane, warpM, warpN);
        __syncthreads();
    }
    gemm_epi<N, NT, BIAS, RELU>(acc, bias, C, nRows, rowBase, colBase,
                                lane, warpM, warpN);
}

// ------------ synchronous GEMM (fp16 A, BN=64) ------------------------------
// A is fp16 (exact in tf32); W must be tf32-pre-rounded.
template <int K, int N, bool BIAS, bool RELU>
__device__ __forceinline__ void gemm_half(const __half* __restrict__ A,
                                          const float* __restrict__ W,
                                          const float* __restrict__ bias,
                                          __half* __restrict__ C, int nRows,
                                          int tileM, float* As, float* Ws) {
    constexpr int BN = 64, NT = 4, WS_STRIDE = 72;
    const int tid = threadIdx.x;
    const int lane = tid & 31;
    const int wid = tid >> 5;
    const int warpM = wid & 3;
    const int warpN = wid >> 2;
    const int rowBase = tileM * 128;

    float acc[2][NT][4];
#pragma unroll
    for (int mt = 0; mt < 2; mt++)
#pragma unroll
        for (int nt = 0; nt < NT; nt++)
#pragma unroll
            for (int i = 0; i < 4; i++) acc[mt][nt][i] = 0.f;

    for (int k0 = 0; k0 < K; k0 += 32) {
#pragma unroll
        for (int i = 0; i < 4; i++) {
            int s = tid + i * 256;
            int m = s >> 3;
            int c4 = (s & 7) * 4;
            float4 v = make_float4(0.f, 0.f, 0.f, 0.f);
            int grow = rowBase + m;
            if (grow < nRows) {
                uint2 u = *(const uint2*)&A[(size_t)grow * K + k0 + c4];
                float2 p0 = __half22float2(*(const __half2*)&u.x);
                float2 p1 = __half22float2(*(const __half2*)&u.y);
                v = make_float4(p0.x, p0.y, p1.x, p1.y);   // exact in tf32
            }
            float* p = &As[m * 36 + c4];
            p[0] = v.x; p[1] = v.y; p[2] = v.z; p[3] = v.w;
        }
#pragma unroll
        for (int i = 0; i < 2; i++) {
            int s = tid + i * 256;
            int r = s >> 4;
            int c4 = (s & 15) * 4;
            *(float4*)&Ws[r * WS_STRIDE + c4] =
                *(const float4*)&W[(size_t)(k0 + r) * N + c4];
        }
        __syncthreads();
        mma_stage<NT, WS_STRIDE, false>(As, Ws, acc, lane, warpM, warpN);
        __syncthreads();
    }
    gemm_epi<N, NT, BIAS, RELU>(acc, bias, C, nRows, rowBase, 0,
                                lane, warpM, warpN);
}

// ---------------- aggregation node body (fp16 gathers, one warp/node) -------
template <int F, bool RELU, bool COMBINE>
__device__ __forceinline__ void agg_node(int gw, const __half* __restrict__ H,
                                         const float* __restrict__ bias,
                                         const __half* __restrict__ FCh,
                                         __half* __restrict__ Out) {
    const int lane = threadIdx.x & 31;
    constexpr int FPT = F / 32;        // 4 or 2
    const int colb = lane * FPT;
    const float di = g_dinv[gw];

    float acc[FPT];
    if constexpr (FPT == 4) {
        uint2 u = *(const uint2*)&H[(size_t)gw * F + colb];
        float2 p0 = __half22float2(*(const __half2*)&u.x);
        float2 p1 = __half22float2(*(const __half2*)&u.y);
        acc[0] = di * p0.x; acc[1] = di * p0.y;
        acc[2] = di * p1.x; acc[3] = di * p1.y;
    } else {
        uint32_t u = *(const uint32_t*)&H[(size_t)gw * F + colb];
        float2 p = __half22float2(*(const __half2*)&u);
        acc[0] = di * p.x; acc[1] = di * p.y;
    }

    int e = g_rowptr[gw];
    const int end = g_rowptr[gw + 1];
    for (; e + 1 < end; e += 2) {
        int s0 = __ldg(&g_col[e]);
        int s1 = __ldg(&g_col[e + 1]);
        float d0 = __ldg(&g_dinv[s0]);
        float d1 = __ldg(&g_dinv[s1]);
        if constexpr (FPT == 4) {
            uint2 u0 = *(const uint2*)&H[(size_t)s0 * F + colb];
            uint2 u1 = *(const uint2*)&H[(size_t)s1 * F + colb];
            float2 a0 = __half22float2(*(const __half2*)&u0.x);
            float2 a1 = __half22float2(*(const __half2*)&u0.y);
            float2 b0 = __half22float2(*(const __half2*)&u1.x);
            float2 b1 = __half22float2(*(const __half2*)&u1.y);
            acc[0] += d0 * a0.x + d1 * b0.x;
            acc[1] += d0 * a0.y + d1 * b0.y;
            acc[2] += d0 * a1.x + d1 * b1.x;
            acc[3] += d0 * a1.y + d1 * b1.y;
        } else {
            uint32_t u0 = *(const uint32_t*)&H[(size_t)s0 * F + colb];
            uint32_t u1 = *(const uint32_t*)&H[(size_t)s1 * F + colb];
            float2 a = __half22float2(*(const __half2*)&u0);
            float2 b = __half22float2(*(const __half2*)&u1);
            acc[0] += d0 * a.x + d1 * b.x;
            acc[1] += d0 * a.y + d1 * b.y;
        }
    }
    if (e < end) {
        int s0 = __ldg(&g_col[e]);
        float d0 = __ldg(&g_dinv[s0]);
        if constexpr (FPT == 4) {
            uint2 u0 = *(const uint2*)&H[(size_t)s0 * F + colb];
            float2 a0 = __half22float2(*(const __half2*)&u0.x);
            float2 a1 = __half22float2(*(const __half2*)&u0.y);
            acc[0] += d0 * a0.x; acc[1] += d0 * a0.y;
            acc[2] += d0 * a1.x; acc[3] += d0 * a1.y;
        } else {
            uint32_t u0 = *(const uint32_t*)&H[(size_t)s0 * F + colb];
            float2 a = __half22float2(*(const __half2*)&u0);
            acc[0] += d0 * a.x; acc[1] += d0 * a.y;
        }
    }

    float fc[FPT];
    if constexpr (COMBINE) {
        if constexpr (FPT == 2) {
            float2 f = __half22float2(*(const __half2*)&FCh[(size_t)gw * F + colb]);
            fc[0] = f.x; fc[1] = f.y;
        } else {
            uint2 u = *(const uint2*)&FCh[(size_t)gw * F + colb];
            float2 f0 = __half22float2(*(const __half2*)&u.x);
            float2 f1 = __half22float2(*(const __half2*)&u.y);
            fc[0] = f0.x; fc[1] = f0.y; fc[2] = f1.x; fc[3] = f1.y;
        }
    }

#pragma unroll
    for (int j = 0; j < FPT; j++) {
        float o = di * acc[j] + bias[colb + j];
        if (RELU) o = fmaxf(o, 0.f);
        if (COMBINE) o = 0.5f * o + 0.5f * fc[j];
        acc[j] = o;
    }
    if constexpr (FPT == 4) {
        uint2 u;
        *(__half2*)&u.x = __floats2half2_rn(acc[0], acc[1]);
        *(__half2*)&u.y = __floats2half2_rn(acc[2], acc[3]);
        *(uint2*)&Out[(size_t)gw * F + colb] = u;
    } else {
        *(__half2*)&Out[(size_t)gw * F + colb] = __floats2half2_rn(acc[0], acc[1]);
    }
}

// ---- fused: H1 GEMM tiles (even blocks) || histogram chunks (odd blocks) ---
__global__ void __launch_bounds__(256, 2) h1hist_k(const float* __restrict__ x,
                                                   __half* __restrict__ H1,
                                                   const int* __restrict__ dst,
                                                   int ne, int mb, int n) {
    extern __shared__ float dyn_sm[];
    const int role = blockIdx.x & 1;
    const int slot = blockIdx.x >> 1;
    if (role == 1) {                               // histogram chunk
        const int nch = gridDim.x >> 1;
        const int per = (ne + nch - 1) / nch;
        const int s = slot * per;
        const int e = min(s + per, ne);
        for (int i = s + (int)threadIdx.x; i < e; i += 256)
            atomicAdd(&g_cnt[dst[i]], 1);
        return;
    }
    if (slot >= mb) return;
    gemm_pipe<DHID, false, false>(x, g_W1r, nullptr, H1, n, slot, 0, dyn_sm);
}

// ---- fused: F1 GEMM tiles (3 of 4 blocks) || CSR-fill chunks (1 of 4) ------
__global__ void __launch_bounds__(256, 2) f1fill_k(const float* __restrict__ x,
                                                   const float* __restrict__ bf1,
                                                   __half* __restrict__ F1,
                                                   const int* __restrict__ ei,
                                                   int ne, int mb, int n) {
    extern __shared__ float dyn_sm[];
    const int role = blockIdx.x & 3;
    const int grp  = blockIdx.x >> 2;
    if (role == 3) {                               // fill chunk
        const int nch = gridDim.x >> 2;
        const int per = (ne + nch - 1) / nch;
        const int s = grp * per;
        const int e = min(s + per, ne);
        for (int i = s + (int)threadIdx.x; i < e; i += 256) {
            int sv = ei[i];
            int dv = ei[ne + i];
            g_col[atomicAdd(&g_cursor[dv], 1)] = sv;
        }
        return;
    }
    const int idx = grp * 3 + role;
    if (idx >= 2 * mb) return;
    gemm_pipe<DFCH, true, true>(x, g_Wf1r, bf1, F1, n, idx % mb, idx / mb, dyn_sm);
}

// ---- fused: agg1 (15 of 16 blocks) || FC GEMM tiles (1 of 16) --------------
__global__ void __launch_bounds__(256) aggfc_k(const __half* __restrict__ H1,
                                               const float* __restrict__ b1,
                                               __half* __restrict__ A1,
                                               const __half* __restrict__ F1,
                                               const float* __restrict__ bf2,
                                               __half* __restrict__ FC,
                                               int n, int mb) {
    __shared__ float smem[128 * 36 + 32 * 72];
    const int local = blockIdx.x & 15;
    const int grp = blockIdx.x >> 4;
    if (local == 15) {                             // FC GEMM tile
        if (grp >= mb) return;
        gemm_half<DFCH, DOUT, true, false>(F1, g_Wf2r, bf2, FC, n, grp,
                                           smem, smem + 128 * 36);
        return;
    }
    const int aggIdx = grp * 15 + local;
    const int gw = aggIdx * 8 + ((int)threadIdx.x >> 5);
    if (gw >= n) return;
    agg_node<DHID, true, false>(gw, H1, b1, nullptr, A1);
}

// ---- plain GEMM (fp16 A): H2 = A1 @ W2 -------------------------------------
__global__ void __launch_bounds__(256, 2) gemmh2_k(const __half* __restrict__ A1,
                                                   __half* __restrict__ H2, int n) {
    __shared__ float As[128 * 36];
    __shared__ float Ws[32 * 72];
    gemm_half<DHID, DOUT, false, false>(A1, g_W2r, nullptr, H2, n, blockIdx.x, As, Ws);
}

// ---- agg2 + combine: z = 0.5*(agg(H2)+b2) + 0.5*FC -------------------------
__global__ void __launch_bounds__(256) agg2z_k(const __half* __restrict__ H2,
                                               const float* __restrict__ b2,
                                               const __half* __restrict__ FC,
                                               __half* __restrict__ Z, int n) {
    const int gw = (blockIdx.x * 256 + threadIdx.x) >> 5;
    if (gw >= n) return;
    agg_node<DOUT, false, true>(gw, H2, b2, FC, Z);
}

// ---------------- decode (fp16 z): out[q] = dot(z[a], z[b]) -----------------
__global__ void __launch_bounds__(256) decodeh_k(const int* __restrict__ eli,
                                                 const __half* __restrict__ zh,
                                                 float* __restrict__ out, int nq) {
    int t = blockIdx.x * 256 + threadIdx.x;
    int q = t >> 4;
    int l = t & 15;
    if (q >= nq) return;
    int a = eli[q];
    int b = eli[nq + q];
    uint2 ua = *(const uint2*)&zh[(size_t)a * DOUT + l * 4];
    uint2 ub = *(const uint2*)&zh[(size_t)b * DOUT + l * 4];
    float2 a0 = __half22float2(*(const __half2*)&ua.x);
    float2 a1 = __half22float2(*(const __half2*)&ua.y);
    float2 b0 = __half22float2(*(const __half2*)&ub.x);
    float2 b1 = __half22float2(*(const __half2*)&ub.y);
    float p = a0.x * b0.x + a0.y * b0.y + a1.x * b1.x + a1.y * b1.y;
    p += __shfl_xor_sync(0xffffffffu, p, 8);
    p += __shfl_xor_sync(0xffffffffu, p, 4);
    p += __shfl_xor_sync(0xffffffffu, p, 2);
    p += __shfl_xor_sync(0xffffffffu, p, 1);
    if (l == 0) out[q] = p;
}

// ---------------- launch ----------------------------------------------------
extern "C" void kernel_launch(void* const* d_in, const int* in_sizes, int n_in,
                              void* d_out, int out_size) {
    const float* x   = (const float*)d_in[0];
    const int*   ei  = (const int*)d_in[1];
    const int*   eli = (const int*)d_in[2];
    const float* W1  = (const float*)d_in[3];
    const float* b1  = (const float*)d_in[4];
    const float* W2  = (const float*)d_in[5];
    const float* b2  = (const float*)d_in[6];
    const float* Wf1 = (const float*)d_in[7];
    const float* bf1 = (const float*)d_in[8];
    const float* Wf2 = (const float*)d_in[9];
    const float* bf2 = (const float*)d_in[10];
    float* out = (float*)d_out;

    const int n  = in_sizes[0] / DIN;
    const int ne = in_sizes[1] / 2;
    const int nq = in_sizes[2] / 2;

    __half *pH1h, *pA1h, *pH2h, *pF1h, *pFCh, *pZh;
    cudaGetSymbolAddress((void**)&pH1h, g_H1h);
    cudaGetSymbolAddress((void**)&pA1h, g_A1h);
    cudaGetSymbolAddress((void**)&pH2h, g_H2h);
    cudaGetSymbolAddress((void**)&pF1h, g_F1h);
    cudaGetSymbolAddress((void**)&pFCh, g_FCh);
    cudaGetSymbolAddress((void**)&pZh,  g_Zh);

    // dynamic smem for pipelined GEMMs: 2 A stages + 2 W stages
    const int PIPE_SMEM = (2 * 128 * 36 + 2 * 32 * 136) * (int)sizeof(float);  // 71680
    cudaFuncSetAttribute(h1hist_k, cudaFuncAttributeMaxDynamicSharedMemorySize, PIPE_SMEM);
    cudaFuncSetAttribute(f1fill_k, cudaFuncAttributeMaxDynamicSharedMemorySize, PIPE_SMEM);

    const int mb = (n + 127) / 128;                 // GEMM row tiles
    const int nb = (n + 255) / 256;                 // scan blocks
    const int aggBlocks = (n * 32 + 255) / 256;     // warp-per-node blocks

    // 0. pre-round weights to tf32 (rna)
    prep_k<<<(DIN * DFCH + 255) / 256, 256>>>(W1, Wf1, W2, Wf2);
    // 1. [H1 GEMM || histogram]
    h1hist_k<<<2 * mb, 256, PIPE_SMEM>>>(x, pH1h, ei + ne, ne, mb, n);
    // 2. rowptr scan
    reduce2_k<<<nb, 256>>>(nb, n);
    scane_k<<<nb, 256>>>(n);
    // 3. [F1 GEMM || CSR fill]
    const int ngrp = (2 * mb + 2) / 3;
    f1fill_k<<<4 * ngrp, 256, PIPE_SMEM>>>(x, bf1, pF1h, ei, ne, mb, n);
    // 4. [agg1 -> A1 || FC GEMM -> FC]
    const int agrp = (aggBlocks + 14) / 15;
    aggfc_k<<<16 * agrp, 256>>>(pH1h, b1, pA1h, pF1h, bf2, pFCh, n, mb);
    // 5. H2 = A1 @ W2
    gemmh2_k<<<mb, 256>>>(pA1h, pH2h, n);
    // 6. z = 0.5*(agg(H2)+b2) + 0.5*FC
    agg2z_k<<<aggBlocks, 256>>>(pH2h, b2, pFCh, pZh, n);
    // 7. edge dot-product decode
    decodeh_k<<<(nq * 16 + 255) / 256, 256>>>(eli, pZh, out, nq);
}

// round 10
// speedup vs baseline: 1.0642x; 1.0439x over previous
#include <cuda_runtime.h>
#include <cuda_fp16.h>
#include <math.h>
#include <stdint.h>

// Problem constants (fixed by the dataset)
#define NN   50000
#define NE   1600000
#define DIN  128
#define DHID 128
#define DOUT 64
#define DFCH 256

// ---------------- scratch (device globals; no allocation allowed) ----------
static __device__ __align__(16) __half g_H1h[NN * DHID];  // dinv * (x @ W1), fp16
static __device__ __align__(16) __half g_A1h[NN * DHID];  // relu(agg1 + b1), fp16
static __device__ __align__(16) __half g_H2h[NN * DOUT];  // dinv * (A1 @ W2), fp16
static __device__ __align__(16) __half g_F1h[NN * DFCH];  // relu(x@Wf1+bf1), fp16
static __device__ __align__(16) __half g_FCh[NN * DOUT];  // F1@Wf2+bf2, fp16
static __device__ __align__(16) __half g_Zh[NN * DOUT];   // 0.5*gcn + 0.5*fc, fp16
// tf32-pre-rounded weights
static __device__ __align__(16) float g_W1r [DIN * DHID];
static __device__ __align__(16) float g_Wf1r[DIN * DFCH];
static __device__ __align__(16) float g_W2r [DHID * DOUT];
static __device__ __align__(16) float g_Wf2r[DFCH * DOUT];
static __device__ int   g_cnt[NN];                        // zero at rest
static __device__ int   g_rowptr[NN + 1];
static __device__ int   g_cursor[NN];
static __device__ int   g_col[NE];
static __device__ float g_dinv[NN];
static __device__ int   g_bsum[256];
static __device__ int   g_tick;                           // zero at rest

// ---------------- TF32 round helper -----------------------------------------
__device__ __forceinline__ float f2tf32(float f) {
    uint32_t u;
    asm("cvt.rna.tf32.f32 %0, %1;" : "=r"(u) : "f"(f));
    return __uint_as_float(u);
}

// ---------------- weight pre-round kernel ------------------------------------
__global__ void prep_k(const float* __restrict__ W1, const float* __restrict__ Wf1,
                       const float* __restrict__ W2, const float* __restrict__ Wf2) {
    int i = blockIdx.x * 256 + threadIdx.x;
    if (i < DIN * DHID)  g_W1r[i]  = f2tf32(W1[i]);
    if (i < DIN * DFCH)  g_Wf1r[i] = f2tf32(Wf1[i]);
    if (i < DHID * DOUT) g_W2r[i]  = f2tf32(W2[i]);
    if (i < DFCH * DOUT) g_Wf2r[i] = f2tf32(Wf2[i]);
}

// ---------------- scan kernels ----------------------------------------------
__global__ void reduce2_k(int nbl, int n) {
    __shared__ int sm[256];
    __shared__ int lastBlk;
    int t = threadIdx.x;
    int i = blockIdx.x * 256 + t;
    sm[t] = (i < n) ? g_cnt[i] : 0;
    __syncthreads();
    for (int d = 128; d > 0; d >>= 1) {
        if (t < d) sm[t] += sm[t + d];
        __syncthreads();
    }
    if (t == 0) {
        g_bsum[blockIdx.x] = sm[0];
        __threadfence();
        lastBlk = (atomicAdd(&g_tick, 1) == nbl - 1);
    }
    __syncthreads();
    if (lastBlk) {
        __threadfence();
        int v = (t < nbl) ? g_bsum[t] : 0;
        sm[t] = v;
        __syncthreads();
        for (int d = 1; d < 256; d <<= 1) {
            int a = (t >= d) ? sm[t - d] : 0;
            __syncthreads();
            sm[t] += a;
            __syncthreads();
        }
        if (t < nbl) g_bsum[t] = sm[t] - v;
        if (t == 0) { g_rowptr[n] = sm[255]; g_tick = 0; }
    }
}

__global__ void scane_k(int n) {
    __shared__ int sm[256];
    int t = threadIdx.x;
    int i = blockIdx.x * 256 + t;
    int v = (i < n) ? g_cnt[i] : 0;
    sm[t] = v;
    __syncthreads();
    for (int d = 1; d < 256; d <<= 1) {
        int a = (t >= d) ? sm[t - d] : 0;
        __syncthreads();
        sm[t] += a;
        __syncthreads();
    }
    if (i < n) {
        int excl = g_bsum[blockIdx.x] + sm[t] - v;
        g_rowptr[i] = excl;
        g_cursor[i] = excl;
        g_dinv[i]   = rsqrtf((float)(v + 1));
        g_cnt[i]    = 0;                       // restore zeroed state
    }
}

// ---------------- mma / cp.async helpers ------------------------------------
__device__ __forceinline__ void mma_tf32(float* d, const uint32_t* a, const uint32_t* b) {
    asm volatile(
        "mma.sync.aligned.m16n8k8.row.col.f32.tf32.tf32.f32 "
        "{%0,%1,%2,%3}, {%4,%5,%6,%7}, {%8,%9}, {%0,%1,%2,%3};"
        : "+f"(d[0]), "+f"(d[1]), "+f"(d[2]), "+f"(d[3])
        : "r"(a[0]), "r"(a[1]), "r"(a[2]), "r"(a[3]), "r"(b[0]), "r"(b[1]));
}

__device__ __forceinline__ uint32_t smem_u32(const void* p) {
    return (uint32_t)__cvta_generic_to_shared(p);
}
__device__ __forceinline__ void cpa16(uint32_t dst, const void* src, int sz) {
    asm volatile("cp.async.cg.shared.global [%0], [%1], 16, %2;"
                 :: "r"(dst), "l"(src), "r"(sz));
}
__device__ __forceinline__ void cpa_commit() {
    asm volatile("cp.async.commit_group;");
}
template <int NP>
__device__ __forceinline__ void cpa_wait() {
    asm volatile("cp.async.wait_group %0;" :: "n"(NP));
}

// ------------ mma compute core over one (As, Ws) stage ----------------------
template <int NT, int WS_STRIDE, bool CVT_A>
__device__ __forceinline__ void mma_stage(const float* As, const float* Ws,
                                          float acc[2][NT][4],
                                          int lane, int warpM, int warpN) {
#pragma unroll
    for (int ks = 0; ks < 4; ks++) {
        const int k8 = ks * 8;
        uint32_t a[2][4];
#pragma unroll
        for (int mt = 0; mt < 2; mt++) {
            const float* Ap = &As[(warpM * 32 + mt * 16 + (lane >> 2)) * 36
                                  + k8 + (lane & 3)];
            float v0 = Ap[0];
            float v1 = Ap[8 * 36];
            float v2 = Ap[4];
            float v3 = Ap[8 * 36 + 4];
            if (CVT_A) {
                v0 = f2tf32(v0); v1 = f2tf32(v1);
                v2 = f2tf32(v2); v3 = f2tf32(v3);
            }
            a[mt][0] = __float_as_uint(v0);
            a[mt][1] = __float_as_uint(v1);
            a[mt][2] = __float_as_uint(v2);
            a[mt][3] = __float_as_uint(v3);
        }
#pragma unroll
        for (int nt = 0; nt < NT; nt++) {
            const int n0 = warpN * (NT * 8) + nt * 8 + (lane >> 2);
            uint32_t b[2];
            b[0] = __float_as_uint(Ws[(k8 + (lane & 3)) * WS_STRIDE + n0]);
            b[1] = __float_as_uint(Ws[(k8 + (lane & 3) + 4) * WS_STRIDE + n0]);
            mma_tf32(acc[0][nt], a[0], b);
            mma_tf32(acc[1][nt], a[1], b);
        }
    }
}

// ------------ epilogue: bias/relu/dinv-scale, fp16 store --------------------
template <int N, int NT, bool BIAS, bool RELU, bool SCALE>
__device__ __forceinline__ void gemm_epi(float acc[2][NT][4],
                                         const float* __restrict__ bias,
                                         __half* __restrict__ C, int nRows,
                                         int rowBase, int colBase,
                                         int lane, int warpM, int warpN) {
#pragma unroll
    for (int mt = 0; mt < 2; mt++) {
#pragma unroll
        for (int half = 0; half < 2; half++) {
            int row = rowBase + warpM * 32 + mt * 16 + (lane >> 2) + half * 8;
            if (row >= nRows) continue;
            float dsc = SCALE ? g_dinv[row] : 1.f;
#pragma unroll
            for (int nt = 0; nt < NT; nt++) {
                int col = colBase + warpN * (NT * 8) + nt * 8 + (lane & 3) * 2;
                float v0 = acc[mt][nt][half * 2 + 0];
                float v1 = acc[mt][nt][half * 2 + 1];
                if (BIAS) { v0 += bias[col]; v1 += bias[col + 1]; }
                if (RELU) { v0 = fmaxf(v0, 0.f); v1 = fmaxf(v1, 0.f); }
                if (SCALE) { v0 *= dsc; v1 *= dsc; }
                *(__half2*)&C[(size_t)row * N + col] = __floats2half2_rn(v0, v1);
            }
        }
    }
}

// ------------ pipelined GEMM (fp32 A, K=128, BM=128, BN=128, cp.async) ------
template <int N, bool BIAS, bool RELU, bool SCALE>
__device__ __forceinline__ void gemm_pipe(const float* __restrict__ A,
                                          const float* __restrict__ W,
                                          const float* __restrict__ bias,
                                          __half* __restrict__ C, int nRows,
                                          int tileM, int colBlk, float* sm) {
    constexpr int K = 128, BN = 128, NT = 8;
    constexpr int ASZ = 128 * 36;
    constexpr int WSZ = 32 * 136;
    float* Asb[2] = {sm, sm + ASZ};
    float* Wsb[2] = {sm + 2 * ASZ, sm + 2 * ASZ + WSZ};

    const int tid = threadIdx.x;
    const int lane = tid & 31;
    const int wid = tid >> 5;
    const int warpM = wid & 3;
    const int warpN = wid >> 2;
    const int rowBase = tileM * 128;
    const int colBase = colBlk * BN;

    auto loadStage = [&](int st, int k0) {
#pragma unroll
        for (int i = 0; i < 4; i++) {
            int s = tid + i * 256;
            int m = s >> 3;
            int c4 = (s & 7) * 4;
            int grow = rowBase + m;
            int ok = grow < nRows;
            const float* src = &A[(size_t)(ok ? grow : 0) * K + k0 + c4];
            cpa16(smem_u32(&Asb[st][m * 36 + c4]), src, ok ? 16 : 0);
        }
#pragma unroll
        for (int i = 0; i < 4; i++) {
            int s = tid + i * 256;
            int r = s >> 5;
            int c4 = (s & 31) * 4;
            cpa16(smem_u32(&Wsb[st][r * 136 + c4]),
                  &W[(size_t)(k0 + r) * N + colBase + c4], 16);
        }
        cpa_commit();
    };

    float acc[2][NT][4];
#pragma unroll
    for (int mt = 0; mt < 2; mt++)
#pragma unroll
        for (int nt = 0; nt < NT; nt++)
#pragma unroll
            for (int i = 0; i < 4; i++) acc[mt][nt][i] = 0.f;

    loadStage(0, 0);
#pragma unroll
    for (int it = 0; it < 4; it++) {
        int st = it & 1;
        if (it < 3) loadStage(st ^ 1, (it + 1) * 32);
        if (it < 3) cpa_wait<1>(); else cpa_wait<0>();
        __syncthreads();
        mma_stage<NT, 136, true>(Asb[st], Wsb[st], acc, lane, warpM, warpN);
        __syncthreads();
    }
    gemm_epi<N, NT, BIAS, RELU, SCALE>(acc, bias, C, nRows, rowBase, colBase,
                                       lane, warpM, warpN);
}

// ------------ synchronous GEMM (fp16 A, BN=64) ------------------------------
template <int K, int N, bool BIAS, bool RELU, bool SCALE>
__device__ __forceinline__ void gemm_half(const __half* __restrict__ A,
                                          const float* __restrict__ W,
                                          const float* __restrict__ bias,
                                          __half* __restrict__ C, int nRows,
                                          int tileM, float* As, float* Ws) {
    constexpr int BN = 64, NT = 4, WS_STRIDE = 72;
    const int tid = threadIdx.x;
    const int lane = tid & 31;
    const int wid = tid >> 5;
    const int warpM = wid & 3;
    const int warpN = wid >> 2;
    const int rowBase = tileM * 128;

    float acc[2][NT][4];
#pragma unroll
    for (int mt = 0; mt < 2; mt++)
#pragma unroll
        for (int nt = 0; nt < NT; nt++)
#pragma unroll
            for (int i = 0; i < 4; i++) acc[mt][nt][i] = 0.f;

    for (int k0 = 0; k0 < K; k0 += 32) {
#pragma unroll
        for (int i = 0; i < 4; i++) {
            int s = tid + i * 256;
            int m = s >> 3;
            int c4 = (s & 7) * 4;
            float4 v = make_float4(0.f, 0.f, 0.f, 0.f);
            int grow = rowBase + m;
            if (grow < nRows) {
                uint2 u = *(const uint2*)&A[(size_t)grow * K + k0 + c4];
                float2 p0 = __half22float2(*(const __half2*)&u.x);
                float2 p1 = __half22float2(*(const __half2*)&u.y);
                v = make_float4(p0.x, p0.y, p1.x, p1.y);   // exact in tf32
            }
            float* p = &As[m * 36 + c4];
            p[0] = v.x; p[1] = v.y; p[2] = v.z; p[3] = v.w;
        }
#pragma unroll
        for (int i = 0; i < 2; i++) {
            int s = tid + i * 256;
            int r = s >> 4;
            int c4 = (s & 15) * 4;
            *(float4*)&Ws[r * WS_STRIDE + c4] =
                *(const float4*)&W[(size_t)(k0 + r) * N + c4];
        }
        __syncthreads();
        mma_stage<NT, WS_STRIDE, false>(As, Ws, acc, lane, warpM, warpN);
        __syncthreads();
    }
    gemm_epi<N, NT, BIAS, RELU, SCALE>(acc, bias, C, nRows, rowBase, 0,
                                       lane, warpM, warpN);
}

// ---------------- aggregation node body --------------------------------------
// H is PRESCALED by dinv (H'[i] = dinv[i]*H[i]). Pure gather-sum, 4-edge unroll.
// out = maybe_relu / combine( di * (H'[gw] + sum_e H'[col[e]]) + bias ).
template <int F, bool RELU, bool COMBINE>
__device__ __forceinline__ void agg_node(int gw, const __half* __restrict__ H,
                                         const float* __restrict__ bias,
                                         const __half* __restrict__ FCh,
                                         __half* __restrict__ Out) {
    const int lane = threadIdx.x & 31;
    constexpr int FPT = F / 32;        // 4 or 2
    const int colb = lane * FPT;
    const float di = g_dinv[gw];

    float acc[FPT];
    if constexpr (FPT == 4) {
        uint2 u = *(const uint2*)&H[(size_t)gw * F + colb];
        float2 p0 = __half22float2(*(const __half2*)&u.x);
        float2 p1 = __half22float2(*(const __half2*)&u.y);
        acc[0] = p0.x; acc[1] = p0.y; acc[2] = p1.x; acc[3] = p1.y;
    } else {
        uint32_t u = *(const uint32_t*)&H[(size_t)gw * F + colb];
        float2 p = __half22float2(*(const __half2*)&u);
        acc[0] = p.x; acc[1] = p.y;
    }

    int e = g_rowptr[gw];
    const int end = g_rowptr[gw + 1];
    // 4-edge unrolled pure-sum loop (MLP 4)
    for (; e + 3 < end; e += 4) {
        int s0 = __ldg(&g_col[e + 0]);
        int s1 = __ldg(&g_col[e + 1]);
        int s2 = __ldg(&g_col[e + 2]);
        int s3 = __ldg(&g_col[e + 3]);
        if constexpr (FPT == 4) {
            uint2 u0 = *(const uint2*)&H[(size_t)s0 * F + colb];
            uint2 u1 = *(const uint2*)&H[(size_t)s1 * F + colb];
            uint2 u2 = *(const uint2*)&H[(size_t)s2 * F + colb];
            uint2 u3 = *(const uint2*)&H[(size_t)s3 * F + colb];
            float2 a0 = __half22float2(*(const __half2*)&u0.x);
            float2 a1 = __half22float2(*(const __half2*)&u0.y);
            float2 b0 = __half22float2(*(const __half2*)&u1.x);
            float2 b1 = __half22float2(*(const __half2*)&u1.y);
            float2 c0 = __half22float2(*(const __half2*)&u2.x);
            float2 c1 = __half22float2(*(const __half2*)&u2.y);
            float2 d0 = __half22float2(*(const __half2*)&u3.x);
            float2 d1 = __half22float2(*(const __half2*)&u3.y);
            acc[0] += (a0.x + b0.x) + (c0.x + d0.x);
            acc[1] += (a0.y + b0.y) + (c0.y + d0.y);
            acc[2] += (a1.x + b1.x) + (c1.x + d1.x);
            acc[3] += (a1.y + b1.y) + (c1.y + d1.y);
        } else {
            uint32_t u0 = *(const uint32_t*)&H[(size_t)s0 * F + colb];
            uint32_t u1 = *(const uint32_t*)&H[(size_t)s1 * F + colb];
            uint32_t u2 = *(const uint32_t*)&H[(size_t)s2 * F + colb];
            uint32_t u3 = *(const uint32_t*)&H[(size_t)s3 * F + colb];
            float2 a = __half22float2(*(const __half2*)&u0);
            float2 b = __half22float2(*(const __half2*)&u1);
            float2 c = __half22float2(*(const __half2*)&u2);
            float2 d = __half22float2(*(const __half2*)&u3);
            acc[0] += (a.x + b.x) + (c.x + d.x);
            acc[1] += (a.y + b.y) + (c.y + d.y);
        }
    }
    for (; e < end; e++) {
        int s0 = __ldg(&g_col[e]);
        if constexpr (FPT == 4) {
            uint2 u0 = *(const uint2*)&H[(size_t)s0 * F + colb];
            float2 a0 = __half22float2(*(const __half2*)&u0.x);
            float2 a1 = __half22float2(*(const __half2*)&u0.y);
            acc[0] += a0.x; acc[1] += a0.y;
            acc[2] += a1.x; acc[3] += a1.y;
        } else {
            uint32_t u0 = *(const uint32_t*)&H[(size_t)s0 * F + colb];
            float2 a = __half22float2(*(const __half2*)&u0);
            acc[0] += a.x; acc[1] += a.y;
        }
    }

    float fc[FPT];
    if constexpr (COMBINE) {
        if constexpr (FPT == 2) {
            float2 f = __half22float2(*(const __half2*)&FCh[(size_t)gw * F + colb]);
            fc[0] = f.x; fc[1] = f.y;
        } else {
            uint2 u = *(const uint2*)&FCh[(size_t)gw * F + colb];
            float2 f0 = __half22float2(*(const __half2*)&u.x);
            float2 f1 = __half22float2(*(const __half2*)&u.y);
            fc[0] = f0.x; fc[1] = f0.y; fc[2] = f1.x; fc[3] = f1.y;
        }
    }

#pragma unroll
    for (int j = 0; j < FPT; j++) {
        float o = di * acc[j] + bias[colb + j];
        if (RELU) o = fmaxf(o, 0.f);
        if (COMBINE) o = 0.5f * o + 0.5f * fc[j];
        acc[j] = o;
    }
    if constexpr (FPT == 4) {
        uint2 u;
        *(__half2*)&u.x = __floats2half2_rn(acc[0], acc[1]);
        *(__half2*)&u.y = __floats2half2_rn(acc[2], acc[3]);
        *(uint2*)&Out[(size_t)gw * F + colb] = u;
    } else {
        *(__half2*)&Out[(size_t)gw * F + colb] = __floats2half2_rn(acc[0], acc[1]);
    }
}

// ---- fused: F1 GEMM tiles (3 of 4 blocks) || histogram chunks (1 of 4) -----
__global__ void __launch_bounds__(256, 2) f1hist_k(const float* __restrict__ x,
                                                   const float* __restrict__ bf1,
                                                   __half* __restrict__ F1,
                                                   const int* __restrict__ dst,
                                                   int ne, int mb, int n) {
    extern __shared__ float dyn_sm[];
    const int role = blockIdx.x & 3;
    const int grp  = blockIdx.x >> 2;
    if (role == 3) {                               // histogram chunk
        const int nch = gridDim.x >> 2;
        const int per = (ne + nch - 1) / nch;
        const int s = grp * per;
        const int e = min(s + per, ne);
        for (int i = s + (int)threadIdx.x; i < e; i += 256)
            atomicAdd(&g_cnt[dst[i]], 1);
        return;
    }
    const int idx = grp * 3 + role;
    if (idx >= 2 * mb) return;
    gemm_pipe<DFCH, true, true, false>(x, g_Wf1r, bf1, F1, n, idx % mb, idx / mb, dyn_sm);
}

// ---- fused: H1 GEMM (dinv-scaled; 2 of 3 blocks) || CSR-fill (1 of 3) ------
__global__ void __launch_bounds__(256, 2) h1fill_k(const float* __restrict__ x,
                                                   __half* __restrict__ H1,
                                                   const int* __restrict__ ei,
                                                   int ne, int mb, int n) {
    extern __shared__ float dyn_sm[];
    const int role = blockIdx.x % 3;
    const int grp  = blockIdx.x / 3;
    if (role == 2) {                               // fill chunk
        const int nch = gridDim.x / 3;
        const int per = (ne + nch - 1) / nch;
        const int s = grp * per;
        const int e = min(s + per, ne);
        for (int i = s + (int)threadIdx.x; i < e; i += 256) {
            int sv = ei[i];
            int dv = ei[ne + i];
            g_col[atomicAdd(&g_cursor[dv], 1)] = sv;
        }
        return;
    }
    const int idx = grp * 2 + role;
    if (idx >= mb) return;
    gemm_pipe<DHID, false, false, true>(x, g_W1r, nullptr, H1, n, idx, 0, dyn_sm);
}

// ---- fused: agg1 (15 of 16 blocks) || FC GEMM tiles (1 of 16) --------------
__global__ void __launch_bounds__(256) aggfc_k(const __half* __restrict__ H1,
                                               const float* __restrict__ b1,
                                               __half* __restrict__ A1,
                                               const __half* __restrict__ F1,
                                               const float* __restrict__ bf2,
                                               __half* __restrict__ FC,
                                               int n, int mb) {
    __shared__ float smem[128 * 36 + 32 * 72];
    const int local = blockIdx.x & 15;
    const int grp = blockIdx.x >> 4;
    if (local == 15) {                             // FC GEMM tile
        if (grp >= mb) return;
        gemm_half<DFCH, DOUT, true, false, false>(F1, g_Wf2r, bf2, FC, n, grp,
                                                  smem, smem + 128 * 36);
        return;
    }
    const int aggIdx = grp * 15 + local;
    const int gw = aggIdx * 8 + ((int)threadIdx.x >> 5);
    if (gw >= n) return;
    agg_node<DHID, true, false>(gw, H1, b1, nullptr, A1);
}

// ---- plain GEMM (fp16 A): H2' = dinv * (A1 @ W2) ---------------------------
__global__ void __launch_bounds__(256, 2) gemmh2_k(const __half* __restrict__ A1,
                                                   __half* __restrict__ H2, int n) {
    __shared__ float As[128 * 36];
    __shared__ float Ws[32 * 72];
    gemm_half<DHID, DOUT, false, false, true>(A1, g_W2r, nullptr, H2, n, blockIdx.x,
                                              As, Ws);
}

// ---- agg2 + combine: z = 0.5*(agg(H2')+b2) + 0.5*FC ------------------------
__global__ void __launch_bounds__(256) agg2z_k(const __half* __restrict__ H2,
                                               const float* __restrict__ b2,
                                               const __half* __restrict__ FC,
                                               __half* __restrict__ Z, int n) {
    const int gw = (blockIdx.x * 256 + threadIdx.x) >> 5;
    if (gw >= n) return;
    agg_node<DOUT, false, true>(gw, H2, b2, FC, Z);
}

// ---------------- decode (fp16 z): out[q] = dot(z[a], z[b]) -----------------
__global__ void __launch_bounds__(256) decodeh_k(const int* __restrict__ eli,
                                                 const __half* __restrict__ zh,
                                                 float* __restrict__ out, int nq) {
    int t = blockIdx.x * 256 + threadIdx.x;
    int q = t >> 4;
    int l = t & 15;
    if (q >= nq) return;
    int a = eli[q];
    int b = eli[nq + q];
    uint2 ua = *(const uint2*)&zh[(size_t)a * DOUT + l * 4];
    uint2 ub = *(const uint2*)&zh[(size_t)b * DOUT + l * 4];
    float2 a0 = __half22float2(*(const __half2*)&ua.x);
    float2 a1 = __half22float2(*(const __half2*)&ua.y);
    float2 b0 = __half22float2(*(const __half2*)&ub.x);
    float2 b1 = __half22float2(*(const __half2*)&ub.y);
    float p = a0.x * b0.x + a0.y * b0.y + a1.x * b1.x + a1.y * b1.y;
    p += __shfl_xor_sync(0xffffffffu, p, 8);
    p += __shfl_xor_sync(0xffffffffu, p, 4);
    p += __shfl_xor_sync(0xffffffffu, p, 2);
    p += __shfl_xor_sync(0xffffffffu, p, 1);
    if (l == 0) out[q] = p;
}

// ---------------- launch ----------------------------------------------------
extern "C" void kernel_launch(void* const* d_in, const int* in_sizes, int n_in,
                              void* d_out, int out_size) {
    const float* x   = (const float*)d_in[0];
    const int*   ei  = (const int*)d_in[1];
    const int*   eli = (const int*)d_in[2];
    const float* W1  = (const float*)d_in[3];
    const float* b1  = (const float*)d_in[4];
    const float* W2  = (const float*)d_in[5];
    const float* b2  = (const float*)d_in[6];
    const float* Wf1 = (const float*)d_in[7];
    const float* bf1 = (const float*)d_in[8];
    const float* Wf2 = (const float*)d_in[9];
    const float* bf2 = (const float*)d_in[10];
    float* out = (float*)d_out;

    const int n  = in_sizes[0] / DIN;
    const int ne = in_sizes[1] / 2;
    const int nq = in_sizes[2] / 2;

    __half *pH1h, *pA1h, *pH2h, *pF1h, *pFCh, *pZh;
    cudaGetSymbolAddress((void**)&pH1h, g_H1h);
    cudaGetSymbolAddress((void**)&pA1h, g_A1h);
    cudaGetSymbolAddress((void**)&pH2h, g_H2h);
    cudaGetSymbolAddress((void**)&pF1h, g_F1h);
    cudaGetSymbolAddress((void**)&pFCh, g_FCh);
    cudaGetSymbolAddress((void**)&pZh,  g_Zh);

    // dynamic smem for pipelined GEMMs: 2 A stages + 2 W stages
    const int PIPE_SMEM = (2 * 128 * 36 + 2 * 32 * 136) * (int)sizeof(float);  // 71680
    cudaFuncSetAttribute(f1hist_k, cudaFuncAttributeMaxDynamicSharedMemorySize, PIPE_SMEM);
    cudaFuncSetAttribute(h1fill_k, cudaFuncAttributeMaxDynamicSharedMemorySize, PIPE_SMEM);

    const int mb = (n + 127) / 128;                 // GEMM row tiles (391)
    const int nb = (n + 255) / 256;                 // scan blocks (196)
    const int aggBlocks = (n * 32 + 255) / 256;     // warp-per-node blocks

    // 0. pre-round weights to tf32 (rna)
    prep_k<<<(DIN * DFCH + 255) / 256, 256>>>(W1, Wf1, W2, Wf2);
    // 1. [F1 GEMM || histogram]   (g_cnt arrives zeroed)
    const int fgrp = (2 * mb + 2) / 3;
    f1hist_k<<<4 * fgrp, 256, PIPE_SMEM>>>(x, bf1, pF1h, ei + ne, ne, mb, n);
    // 2. rowptr scan -> rowptr, cursor, dinv
    reduce2_k<<<nb, 256>>>(nb, n);
    scane_k<<<nb, 256>>>(n);
    // 3. [H1 GEMM (dinv-scaled) || CSR fill]
    const int hgrp = (mb + 1) / 2;
    h1fill_k<<<3 * hgrp, 256, PIPE_SMEM>>>(x, pH1h, ei, ne, mb, n);
    // 4. [agg1 -> A1 || FC GEMM -> FC]
    const int agrp = (aggBlocks + 14) / 15;
    aggfc_k<<<16 * agrp, 256>>>(pH1h, b1, pA1h, pF1h, bf2, pFCh, n, mb);
    // 5. H2' = dinv * (A1 @ W2)
    gemmh2_k<<<mb, 256>>>(pA1h, pH2h, n);
    // 6. z = 0.5*(agg(H2')+b2) + 0.5*FC
    agg2z_k<<<aggBlocks, 256>>>(pH2h, b2, pFCh, pZh, n);
    // 7. edge dot-product decode
    decodeh_k<<<(nq * 16 + 255) / 256, 256>>>(eli, pZh, out, nq);
}

// round 12
// speedup vs baseline: 1.2046x; 1.1320x over previous
#include <cuda_runtime.h>
#include <cuda_fp16.h>
#include <math.h>
#include <stdint.h>

// Problem constants (fixed by the dataset)
#define NN   50000
#define NE   1600000
#define DIN  128
#define DHID 128
#define DOUT 64
#define DFCH 256

// ---------------- scratch (device globals; no allocation allowed) ----------
static __device__ __align__(16) __half g_xh [NN * DIN];   // x, fp16
static __device__ __align__(16) __half g_H1h[NN * DHID];  // dinv * (x @ W1), fp16
static __device__ __align__(16) __half g_A1h[NN * DHID];  // relu(agg1 + b1), fp16
static __device__ __align__(16) __half g_H2h[NN * DOUT];  // dinv * (A1 @ W2), fp16
static __device__ __align__(16) __half g_F1h[NN * DFCH];  // relu(x@Wf1+bf1), fp16
static __device__ __align__(16) __half g_FCh[NN * DOUT];  // F1@Wf2+bf2, fp16
static __device__ __align__(16) __half g_Zh[NN * DOUT];   // 0.5*gcn + 0.5*fc, fp16
// fp16 transposed weights: Wt[n][k]
static __device__ __align__(16) __half g_W1t [DHID * DIN];
static __device__ __align__(16) __half g_Wf1t[DFCH * DIN];
static __device__ __align__(16) __half g_W2t [DOUT * DHID];
static __device__ __align__(16) __half g_Wf2t[DOUT * DFCH];
static __device__ int   g_cnt[NN];                        // zero at rest
static __device__ int   g_rowptr[NN + 1];
static __device__ int   g_cursor[NN];
static __device__ int   g_col[NE];
static __device__ float g_dinv[NN];
static __device__ int   g_bsum[256];
static __device__ int   g_tick;                           // zero at rest

// ---------------- prep: x -> fp16; weights -> fp16 transposed ----------------
__global__ void prep_k(const float* __restrict__ x,
                       const float* __restrict__ W1, const float* __restrict__ Wf1,
                       const float* __restrict__ W2, const float* __restrict__ Wf2,
                       int nx4) {
    int i = blockIdx.x * 256 + threadIdx.x;
    if (i < nx4) {
        float4 v = *(const float4*)&x[(size_t)i * 4];
        uint2 u;
        *(__half2*)&u.x = __floats2half2_rn(v.x, v.y);
        *(__half2*)&u.y = __floats2half2_rn(v.z, v.w);
        *(uint2*)&g_xh[(size_t)i * 4] = u;
        return;
    }
    int j = i - nx4;
    if (j < DIN * DHID) {
        int nn = j / DIN, k = j % DIN;
        g_W1t[j] = __float2half(W1[k * DHID + nn]);
        return;
    }
    j -= DIN * DHID;
    if (j < DIN * DFCH) {
        int nn = j / DIN, k = j % DIN;
        g_Wf1t[j] = __float2half(Wf1[k * DFCH + nn]);
        return;
    }
    j -= DIN * DFCH;
    if (j < DHID * DOUT) {
        int nn = j / DHID, k = j % DHID;
        g_W2t[j] = __float2half(W2[k * DOUT + nn]);
        return;
    }
    j -= DHID * DOUT;
    if (j < DFCH * DOUT) {
        int nn = j / DFCH, k = j % DFCH;
        g_Wf2t[j] = __float2half(Wf2[k * DOUT + nn]);
    }
}

// ---------------- scan kernels ----------------------------------------------
__global__ void reduce2_k(int nbl, int n) {
    __shared__ int sm[256];
    __shared__ int lastBlk;
    int t = threadIdx.x;
    int i = blockIdx.x * 256 + t;
    sm[t] = (i < n) ? g_cnt[i] : 0;
    __syncthreads();
    for (int d = 128; d > 0; d >>= 1) {
        if (t < d) sm[t] += sm[t + d];
        __syncthreads();
    }
    if (t == 0) {
        g_bsum[blockIdx.x] = sm[0];
        __threadfence();
        lastBlk = (atomicAdd(&g_tick, 1) == nbl - 1);
    }
    __syncthreads();
    if (lastBlk) {
        __threadfence();
        int v = (t < nbl) ? g_bsum[t] : 0;
        sm[t] = v;
        __syncthreads();
        for (int d = 1; d < 256; d <<= 1) {
            int a = (t >= d) ? sm[t - d] : 0;
            __syncthreads();
            sm[t] += a;
            __syncthreads();
        }
        if (t < nbl) g_bsum[t] = sm[t] - v;
        if (t == 0) { g_rowptr[n] = sm[255]; g_tick = 0; }
    }
}

__global__ void scane_k(int n) {
    __shared__ int sm[256];
    int t = threadIdx.x;
    int i = blockIdx.x * 256 + t;
    int v = (i < n) ? g_cnt[i] : 0;
    sm[t] = v;
    __syncthreads();
    for (int d = 1; d < 256; d <<= 1) {
        int a = (t >= d) ? sm[t - d] : 0;
        __syncthreads();
        sm[t] += a;
        __syncthreads();
    }
    if (i < n) {
        int excl = g_bsum[blockIdx.x] + sm[t] - v;
        g_rowptr[i] = excl;
        g_cursor[i] = excl;
        g_dinv[i]   = rsqrtf((float)(v + 1));
        g_cnt[i]    = 0;                       // restore zeroed state
    }
}

// ---------------- mma / cp.async helpers ------------------------------------
__device__ __forceinline__ void mma_f16(float* d, const uint32_t* a, const uint32_t* b) {
    asm volatile(
        "mma.sync.aligned.m16n8k16.row.col.f32.f16.f16.f32 "
        "{%0,%1,%2,%3}, {%4,%5,%6,%7}, {%8,%9}, {%0,%1,%2,%3};"
        : "+f"(d[0]), "+f"(d[1]), "+f"(d[2]), "+f"(d[3])
        : "r"(a[0]), "r"(a[1]), "r"(a[2]), "r"(a[3]), "r"(b[0]), "r"(b[1]));
}

__device__ __forceinline__ uint32_t smem_u32(const void* p) {
    return (uint32_t)__cvta_generic_to_shared(p);
}
__device__ __forceinline__ void cpa16(uint32_t dst, const void* src, int sz) {
    asm volatile("cp.async.cg.shared.global [%0], [%1], 16, %2;"
                 :: "r"(dst), "l"(src), "r"(sz));
}
__device__ __forceinline__ void cpa_commit() {
    asm volatile("cp.async.commit_group;");
}
template <int NP>
__device__ __forceinline__ void cpa_wait() {
    asm volatile("cp.async.wait_group %0;" :: "n"(NP));
}

// ------------ fp16 mma core over one 32-k stage ------------------------------
// As: [128][40] halves (rows of A, k-contig). Wts: [n][WT_STR] halves (k-contig).
// kglob: k offset into Wts rows for this stage. acc[2][NT][4].
template <int NT, int WT_STR>
__device__ __forceinline__ void mma_stage16(const __half* As, const __half* Wts,
                                            int kglob, float acc[2][NT][4],
                                            int lane, int warpM, int warpN) {
#pragma unroll
    for (int kk = 0; kk < 2; kk++) {       // two m16n8k16 steps per 32-k stage
        const int kb = kk * 16;
        uint32_t a[2][4];
#pragma unroll
        for (int mt = 0; mt < 2; mt++) {
            const __half* Ap = &As[(warpM * 32 + mt * 16 + (lane >> 2)) * 40
                                   + kb + (lane & 3) * 2];
            a[mt][0] = *(const uint32_t*)Ap;
            a[mt][1] = *(const uint32_t*)(Ap + 8 * 40);
            a[mt][2] = *(const uint32_t*)(Ap + 8);
            a[mt][3] = *(const uint32_t*)(Ap + 8 * 40 + 8);
        }
#pragma unroll
        for (int nt = 0; nt < NT; nt++) {
            const int n0 = warpN * (NT * 8) + nt * 8 + (lane >> 2);
            const __half* Bp = &Wts[n0 * WT_STR + kglob + kb + (lane & 3) * 2];
            uint32_t b[2];
            b[0] = *(const uint32_t*)Bp;
            b[1] = *(const uint32_t*)(Bp + 8);
            mma_f16(acc[0][nt], a[0], b);
            mma_f16(acc[1][nt], a[1], b);
        }
    }
}

// ------------ epilogue: bias/relu/dinv-scale, fp16 store --------------------
template <int N, int NT, bool BIAS, bool RELU, bool SCALE>
__device__ __forceinline__ void gemm_epi(float acc[2][NT][4],
                                         const float* __restrict__ bias,
                                         __half* __restrict__ C, int nRows,
                                         int rowBase, int colBase,
                                         int lane, int warpM, int warpN) {
#pragma unroll
    for (int mt = 0; mt < 2; mt++) {
#pragma unroll
        for (int half = 0; half < 2; half++) {
            int row = rowBase + warpM * 32 + mt * 16 + (lane >> 2) + half * 8;
            if (row >= nRows) continue;
            float dsc = SCALE ? g_dinv[row] : 1.f;
#pragma unroll
            for (int nt = 0; nt < NT; nt++) {
                int col = colBase + warpN * (NT * 8) + nt * 8 + (lane & 3) * 2;
                float v0 = acc[mt][nt][half * 2 + 0];
                float v1 = acc[mt][nt][half * 2 + 1];
                if (BIAS) { v0 += bias[col]; v1 += bias[col + 1]; }
                if (RELU) { v0 = fmaxf(v0, 0.f); v1 = fmaxf(v1, 0.f); }
                if (SCALE) { v0 *= dsc; v1 *= dsc; }
                *(__half2*)&C[(size_t)row * N + col] = __floats2half2_rn(v0, v1);
            }
        }
    }
}

// ------------ pipelined fp16 GEMM (BN=128, Wt smem-resident, A cp.async) ----
template <int K, int N, bool BIAS, bool RELU, bool SCALE>
__device__ __forceinline__ void gemm16_pipe(const __half* __restrict__ A,
                                            const __half* __restrict__ Wt, // [N][K]
                                            const float* __restrict__ bias,
                                            __half* __restrict__ C, int nRows,
                                            int tileM, int colBase, char* smraw) {
    constexpr int BN = 128, NT = 8;
    constexpr int WT_STR = K + 8;
    __half* Wts = (__half*)smraw;                      // BN * WT_STR halves
    __half* As0 = Wts + BN * WT_STR;
    __half* As1 = As0 + 128 * 40;
    __half* Asb[2] = {As0, As1};

    const int tid = threadIdx.x;
    const int lane = tid & 31;
    const int wid = tid >> 5;
    const int warpM = wid & 3;
    const int warpN = wid >> 2;
    const int rowBase = tileM * 128;

    // Wt tile: BN rows x K halves, loaded once
#pragma unroll
    for (int i = 0; i < BN * K / 8 / 256; i++) {
        int s = tid + i * 256;
        int row = s / (K / 8), c8 = s % (K / 8);
        cpa16(smem_u32(&Wts[row * WT_STR + c8 * 8]),
              &Wt[(size_t)(colBase + row) * K + c8 * 8], 16);
    }
    auto loadA = [&](int st, int k0) {
#pragma unroll
        for (int i = 0; i < 2; i++) {
            int s = tid + i * 256;
            int row = s >> 2, c8 = s & 3;
            int grow = rowBase + row;
            int ok = grow < nRows;
            cpa16(smem_u32(&Asb[st][row * 40 + c8 * 8]),
                  &A[(size_t)(ok ? grow : 0) * K + k0 + c8 * 8], ok ? 16 : 0);
        }
        cpa_commit();
    };

    float acc[2][NT][4];
#pragma unroll
    for (int mt = 0; mt < 2; mt++)
#pragma unroll
        for (int nt = 0; nt < NT; nt++)
#pragma unroll
            for (int i = 0; i < 4; i++) acc[mt][nt][i] = 0.f;

    loadA(0, 0);                                  // group includes Wt loads
    constexpr int NST = K / 32;
#pragma unroll
    for (int it = 0; it < NST; it++) {
        int st = it & 1;
        if (it + 1 < NST) loadA(st ^ 1, (it + 1) * 32);
        if (it + 1 < NST) cpa_wait<1>(); else cpa_wait<0>();
        __syncthreads();
        mma_stage16<NT, WT_STR>(Asb[st], Wts, it * 32, acc, lane, warpM, warpN);
        __syncthreads();
    }
    gemm_epi<N, NT, BIAS, RELU, SCALE>(acc, bias, C, nRows, rowBase, colBase,
                                       lane, warpM, warpN);
}

// ------------ synchronous fp16 GEMM (BN=64, per-stage loads) ----------------
template <int K, int N, bool BIAS, bool RELU, bool SCALE>
__device__ __forceinline__ void gemm16_sync(const __half* __restrict__ A,
                                            const __half* __restrict__ Wt, // [N][K]
                                            const float* __restrict__ bias,
                                            __half* __restrict__ C, int nRows,
                                            int tileM, __half* As, __half* Ws) {
    constexpr int NT = 4;
    const int tid = threadIdx.x;
    const int lane = tid & 31;
    const int wid = tid >> 5;
    const int warpM = wid & 3;
    const int warpN = wid >> 2;
    const int rowBase = tileM * 128;

    float acc[2][NT][4];
#pragma unroll
    for (int mt = 0; mt < 2; mt++)
#pragma unroll
        for (int nt = 0; nt < NT; nt++)
#pragma unroll
            for (int i = 0; i < 4; i++) acc[mt][nt][i] = 0.f;

    for (int k0 = 0; k0 < K; k0 += 32) {
#pragma unroll
        for (int i = 0; i < 2; i++) {
            int s = tid + i * 256;
            int row = s >> 2, c8 = s & 3;
            int grow = rowBase + row;
            uint4 v = make_uint4(0u, 0u, 0u, 0u);
            if (grow < nRows) v = *(const uint4*)&A[(size_t)grow * K + k0 + c8 * 8];
            *(uint4*)&As[row * 40 + c8 * 8] = v;
        }
        {
            int row = tid >> 2, c8 = tid & 3;   // 64 rows x 4 chunks
            *(uint4*)&Ws[row * 40 + c8 * 8] =
                *(const uint4*)&Wt[(size_t)row * K + k0 + c8 * 8];
        }
        __syncthreads();
        mma_stage16<NT, 40>(As, Ws, 0, acc, lane, warpM, warpN);
        __syncthreads();
    }
    gemm_epi<N, NT, BIAS, RELU, SCALE>(acc, bias, C, nRows, rowBase, 0,
                                       lane, warpM, warpN);
}

// ---------------- aggregation node body --------------------------------------
// H is PRESCALED by dinv. Pure gather-sum, 4-edge unroll.
template <int F, bool RELU, bool COMBINE>
__device__ __forceinline__ void agg_node(int gw, const __half* __restrict__ H,
                                         const float* __restrict__ bias,
                                         const __half* __restrict__ FCh,
                                         __half* __restrict__ Out) {
    const int lane = threadIdx.x & 31;
    constexpr int FPT = F / 32;        // 4 or 2
    const int colb = lane * FPT;
    const float di = g_dinv[gw];

    float acc[FPT];
    if constexpr (FPT == 4) {
        uint2 u = *(const uint2*)&H[(size_t)gw * F + colb];
        float2 p0 = __half22float2(*(const __half2*)&u.x);
        float2 p1 = __half22float2(*(const __half2*)&u.y);
        acc[0] = p0.x; acc[1] = p0.y; acc[2] = p1.x; acc[3] = p1.y;
    } else {
        uint32_t u = *(const uint32_t*)&H[(size_t)gw * F + colb];
        float2 p = __half22float2(*(const __half2*)&u);
        acc[0] = p.x; acc[1] = p.y;
    }

    int e = g_rowptr[gw];
    const int end = g_rowptr[gw + 1];
    for (; e + 3 < end; e += 4) {
        int s0 = __ldg(&g_col[e + 0]);
        int s1 = __ldg(&g_col[e + 1]);
        int s2 = __ldg(&g_col[e + 2]);
        int s3 = __ldg(&g_col[e + 3]);
        if constexpr (FPT == 4) {
            uint2 u0 = *(const uint2*)&H[(size_t)s0 * F + colb];
            uint2 u1 = *(const uint2*)&H[(size_t)s1 * F + colb];
            uint2 u2 = *(const uint2*)&H[(size_t)s2 * F + colb];
            uint2 u3 = *(const uint2*)&H[(size_t)s3 * F + colb];
            float2 a0 = __half22float2(*(const __half2*)&u0.x);
            float2 a1 = __half22float2(*(const __half2*)&u0.y);
            float2 b0 = __half22float2(*(const __half2*)&u1.x);
            float2 b1 = __half22float2(*(const __half2*)&u1.y);
            float2 c0 = __half22float2(*(const __half2*)&u2.x);
            float2 c1 = __half22float2(*(const __half2*)&u2.y);
            float2 d0 = __half22float2(*(const __half2*)&u3.x);
            float2 d1 = __half22float2(*(const __half2*)&u3.y);
            acc[0] += (a0.x + b0.x) + (c0.x + d0.x);
            acc[1] += (a0.y + b0.y) + (c0.y + d0.y);
            acc[2] += (a1.x + b1.x) + (c1.x + d1.x);
            acc[3] += (a1.y + b1.y) + (c1.y + d1.y);
        } else {
            uint32_t u0 = *(const uint32_t*)&H[(size_t)s0 * F + colb];
            uint32_t u1 = *(const uint32_t*)&H[(size_t)s1 * F + colb];
            uint32_t u2 = *(const uint32_t*)&H[(size_t)s2 * F + colb];
            uint32_t u3 = *(const uint32_t*)&H[(size_t)s3 * F + colb];
            float2 a = __half22float2(*(const __half2*)&u0);
            float2 b = __half22float2(*(const __half2*)&u1);
            float2 c = __half22float2(*(const __half2*)&u2);
            float2 d = __half22float2(*(const __half2*)&u3);
            acc[0] += (a.x + b.x) + (c.x + d.x);
            acc[1] += (a.y + b.y) + (c.y + d.y);
        }
    }
    for (; e < end; e++) {
        int s0 = __ldg(&g_col[e]);
        if constexpr (FPT == 4) {
            uint2 u0 = *(const uint2*)&H[(size_t)s0 * F + colb];
            float2 a0 = __half22float2(*(const __half2*)&u0.x);
            float2 a1 = __half22float2(*(const __half2*)&u0.y);
            acc[0] += a0.x; acc[1] += a0.y;
            acc[2] += a1.x; acc[3] += a1.y;
        } else {
            uint32_t u0 = *(const uint32_t*)&H[(size_t)s0 * F + colb];
            float2 a = __half22float2(*(const __half2*)&u0);
            acc[0] += a.x; acc[1] += a.y;
        }
    }

    float fc[FPT];
    if constexpr (COMBINE) {
        if constexpr (FPT == 2) {
            float2 f = __half22float2(*(const __half2*)&FCh[(size_t)gw * F + colb]);
            fc[0] = f.x; fc[1] = f.y;
        } else {
            uint2 u = *(const uint2*)&FCh[(size_t)gw * F + colb];
            float2 f0 = __half22float2(*(const __half2*)&u.x);
            float2 f1 = __half22float2(*(const __half2*)&u.y);
            fc[0] = f0.x; fc[1] = f0.y; fc[2] = f1.x; fc[3] = f1.y;
        }
    }

#pragma unroll
    for (int j = 0; j < FPT; j++) {
        float o = di * acc[j] + bias[colb + j];
        if (RELU) o = fmaxf(o, 0.f);
        if (COMBINE) o = 0.5f * o + 0.5f * fc[j];
        acc[j] = o;
    }
    if constexpr (FPT == 4) {
        uint2 u;
        *(__half2*)&u.x = __floats2half2_rn(acc[0], acc[1]);
        *(__half2*)&u.y = __floats2half2_rn(acc[2], acc[3]);
        *(uint2*)&Out[(size_t)gw * F + colb] = u;
    } else {
        *(__half2*)&Out[(size_t)gw * F + colb] = __floats2half2_rn(acc[0], acc[1]);
    }
}

// ---- fused: F1 GEMM tiles (3 of 4 blocks) || histogram chunks (1 of 4) -----
__global__ void __launch_bounds__(256, 2) f1hist_k(const float* __restrict__ bf1,
                                                   const int* __restrict__ dst,
                                                   int ne, int mb, int n) {
    extern __shared__ char dyn_sm[];
    const int role = blockIdx.x & 3;
    const int grp  = blockIdx.x >> 2;
    if (role == 3) {                               // histogram chunk
        const int nch = gridDim.x >> 2;
        const int per = (ne + nch - 1) / nch;
        const int s = grp * per;
        const int e = min(s + per, ne);
        for (int i = s + (int)threadIdx.x; i < e; i += 256)
            atomicAdd(&g_cnt[dst[i]], 1);
        return;
    }
    const int idx = grp * 3 + role;
    if (idx >= 2 * mb) return;
    gemm16_pipe<DIN, DFCH, true, true, false>(g_xh, g_Wf1t, bf1, g_F1h, n,
                                              idx % mb, (idx / mb) * 128, dyn_sm);
}

// ---- fused: H1 GEMM (dinv-scaled; 2 of 3 blocks) || CSR-fill (1 of 3) ------
__global__ void __launch_bounds__(256, 2) h1fill_k(const int* __restrict__ ei,
                                                   int ne, int mb, int n) {
    extern __shared__ char dyn_sm[];
    const int role = blockIdx.x % 3;
    const int grp  = blockIdx.x / 3;
    if (role == 2) {                               // fill chunk
        const int nch = gridDim.x / 3;
        const int per = (ne + nch - 1) / nch;
        const int s = grp * per;
        const int e = min(s + per, ne);
        for (int i = s + (int)threadIdx.x; i < e; i += 256) {
            int sv = ei[i];
            int dv = ei[ne + i];
            g_col[atomicAdd(&g_cursor[dv], 1)] = sv;
        }
        return;
    }
    const int idx = grp * 2 + role;
    if (idx >= mb) return;
    gemm16_pipe<DIN, DHID, false, false, true>(g_xh, g_W1t, nullptr, g_H1h, n,
                                               idx, 0, dyn_sm);
}

// ---- fused: agg1 (15 of 16 blocks) || FC GEMM tiles (1 of 16) --------------
__global__ void __launch_bounds__(256) aggfc_k(const float* __restrict__ b1,
                                               const float* __restrict__ bf2,
                                               int n, int mb) {
    __shared__ __half smem[128 * 40 + 64 * 40];
    const int local = blockIdx.x & 15;
    const int grp = blockIdx.x >> 4;
    if (local == 15) {                             // FC GEMM tile
        if (grp >= mb) return;
        gemm16_sync<DFCH, DOUT, true, false, false>(g_F1h, g_Wf2t, bf2, g_FCh, n,
                                                    grp, smem, smem + 128 * 40);
        return;
    }
    const int aggIdx = grp * 15 + local;
    const int gw = aggIdx * 8 + ((int)threadIdx.x >> 5);
    if (gw >= n) return;
    agg_node<DHID, true, false>(gw, g_H1h, b1, nullptr, g_A1h);
}

// ---- GEMM: H2' = dinv * (A1 @ W2) ------------------------------------------
__global__ void __launch_bounds__(256) gemmh2_k(int n) {
    __shared__ __half smem[128 * 40 + 64 * 40];
    gemm16_sync<DHID, DOUT, false, false, true>(g_A1h, g_W2t, nullptr, g_H2h, n,
                                                blockIdx.x, smem, smem + 128 * 40);
}

// ---- agg2 + combine: z = 0.5*(agg(H2')+b2) + 0.5*FC -------------------------
__global__ void __launch_bounds__(256) agg2z_k(const float* __restrict__ b2, int n) {
    const int gw = (blockIdx.x * 256 + threadIdx.x) >> 5;
    if (gw >= n) return;
    agg_node<DOUT, false, true>(gw, g_H2h, b2, g_FCh, g_Zh);
}

// ---------------- decode (fp16 z): out[q] = dot(z[a], z[b]) -----------------
__global__ void __launch_bounds__(256) decodeh_k(const int* __restrict__ eli,
                                                 float* __restrict__ out, int nq) {
    int t = blockIdx.x * 256 + threadIdx.x;
    int q = t >> 4;
    int l = t & 15;
    if (q >= nq) return;
    int a = eli[q];
    int b = eli[nq + q];
    uint2 ua = *(const uint2*)&g_Zh[(size_t)a * DOUT + l * 4];
    uint2 ub = *(const uint2*)&g_Zh[(size_t)b * DOUT + l * 4];
    float2 a0 = __half22float2(*(const __half2*)&ua.x);
    float2 a1 = __half22float2(*(const __half2*)&ua.y);
    float2 b0 = __half22float2(*(const __half2*)&ub.x);
    float2 b1 = __half22float2(*(const __half2*)&ub.y);
    float p = a0.x * b0.x + a0.y * b0.y + a1.x * b1.x + a1.y * b1.y;
    p += __shfl_xor_sync(0xffffffffu, p, 8);
    p += __shfl_xor_sync(0xffffffffu, p, 4);
    p += __shfl_xor_sync(0xffffffffu, p, 2);
    p += __shfl_xor_sync(0xffffffffu, p, 1);
    if (l == 0) out[q] = p;
}

// ---------------- launch ----------------------------------------------------
extern "C" void kernel_launch(void* const* d_in, const int* in_sizes, int n_in,
                              void* d_out, int out_size) {
    const float* x   = (const float*)d_in[0];
    const int*   ei  = (const int*)d_in[1];
    const int*   eli = (const int*)d_in[2];
    const float* W1  = (const float*)d_in[3];
    const float* b1  = (const float*)d_in[4];
    const float* W2  = (const float*)d_in[5];
    const float* b2  = (const float*)d_in[6];
    const float* Wf1 = (const float*)d_in[7];
    const float* bf1 = (const float*)d_in[8];
    const float* Wf2 = (const float*)d_in[9];
    const float* bf2 = (const float*)d_in[10];
    float* out = (float*)d_out;

    const int n  = in_sizes[0] / DIN;
    const int ne = in_sizes[1] / 2;
    const int nq = in_sizes[2] / 2;

    // dynamic smem for pipelined fp16 GEMMs (K=128):
    // Wt tile 128*(128+8) + 2 A stages 128*40*2, all halves
    const int PIPE_SMEM = (128 * 136 + 2 * 128 * 40) * 2;   // 55296 B
    cudaFuncSetAttribute(f1hist_k, cudaFuncAttributeMaxDynamicSharedMemorySize, PIPE_SMEM);
    cudaFuncSetAttribute(h1fill_k, cudaFuncAttributeMaxDynamicSharedMemorySize, PIPE_SMEM);

    const int mb = (n + 127) / 128;                 // GEMM row tiles (391)
    const int nb = (n + 255) / 256;                 // scan blocks (196)
    const int aggBlocks = (n * 32 + 255) / 256;     // warp-per-node blocks
    const int nx4 = (n * DIN) / 4;
    const int wtot = DIN * DHID + DIN * DFCH + DHID * DOUT + DFCH * DOUT;

    // 0. convert x -> fp16; weights -> fp16 transposed
    prep_k<<<(nx4 + wtot + 255) / 256, 256>>>(x, W1, Wf1, W2, Wf2, nx4);
    // 1. [F1 GEMM || histogram]   (g_cnt arrives zeroed)
    const int fgrp = (2 * mb + 2) / 3;
    f1hist_k<<<4 * fgrp, 256, PIPE_SMEM>>>(bf1, ei + ne, ne, mb, n);
    // 2. rowptr scan -> rowptr, cursor, dinv
    reduce2_k<<<nb, 256>>>(nb, n);
    scane_k<<<nb, 256>>>(n);
    // 3. [H1 GEMM (dinv-scaled) || CSR fill]
    const int hgrp = (mb + 1) / 2;
    h1fill_k<<<3 * hgrp, 256, PIPE_SMEM>>>(ei, ne, mb, n);
    // 4. [agg1 -> A1 || FC GEMM -> FC]
    const int agrp = (aggBlocks + 14) / 15;
    aggfc_k<<<16 * agrp, 256>>>(b1, bf2, n, mb);
    // 5. H2' = dinv * (A1 @ W2)
    gemmh2_k<<<mb, 256>>>(n);
    // 6. z = 0.5*(agg(H2')+b2) + 0.5*FC
    agg2z_k<<<aggBlocks, 256>>>(b2, n);
    // 7. edge dot-product decode
    decodeh_k<<<(nq * 16 + 255) / 256, 256>>>(eli, out, nq);
}

// round 14
// speedup vs baseline: 1.3095x; 1.0871x over previous
#include <cuda_runtime.h>
#include <cuda_fp16.h>
#include <math.h>
#include <stdint.h>

// Problem constants (fixed by the dataset)
#define NN   50000
#define NE   1600000
#define DIN  128
#define DHID 128
#define DOUT 64
#define DFCH 256

// ---------------- scratch (device globals; no allocation allowed) ----------
static __device__ __align__(16) __half g_xh [NN * DIN];   // x, fp16
static __device__ __align__(16) __half g_H1h[NN * DHID];  // dinv * (x @ W1), fp16
static __device__ __align__(16) __half g_A1h[NN * DHID];  // relu(agg1 + b1), fp16
static __device__ __align__(16) __half g_H2h[NN * DOUT];  // dinv * (A1 @ W2), fp16
static __device__ __align__(16) __half g_F1h[NN * DFCH];  // relu(x@Wf1+bf1), fp16
static __device__ __align__(16) __half g_FCh[NN * DOUT];  // F1@Wf2+bf2, fp16
static __device__ __align__(16) __half g_Zh[NN * DOUT];   // 0.5*gcn + 0.5*fc, fp16
// fp16 transposed weights: Wt[n][k]
static __device__ __align__(16) __half g_W1t [DHID * DIN];
static __device__ __align__(16) __half g_Wf1t[DFCH * DIN];
static __device__ __align__(16) __half g_W2t [DOUT * DHID];
static __device__ __align__(16) __half g_Wf2t[DOUT * DFCH];
static __device__ int   g_cnt[NN];                        // zero at rest
static __device__ int   g_rowptr[NN + 1];
static __device__ int   g_cursor[NN];
static __device__ int   g_col[NE];
static __device__ float g_dinv[NN];
static __device__ int   g_bsum[256];
static __device__ int   g_tick;                           // zero at rest
static __device__ int   g_flag;                           // zero at rest
static __device__ int   g_done;                           // zero at rest

// ---------------- fused prep (x->fp16, weights->fp16^T) || histogram --------
__global__ void prephist_k(const float* __restrict__ x,
                           const float* __restrict__ W1, const float* __restrict__ Wf1,
                           const float* __restrict__ W2, const float* __restrict__ Wf2,
                           const int* __restrict__ dst,
                           int nx4, int nitems, int ne) {
    const int role = blockIdx.x & 3;
    const int grp  = blockIdx.x >> 2;
    if (role == 3) {                               // histogram chunk
        const int nch = gridDim.x >> 2;
        const int per = (ne + nch - 1) / nch;
        const int s = grp * per;
        const int e = min(s + per, ne);
        for (int i = s + (int)threadIdx.x; i < e; i += 256)
            atomicAdd(&g_cnt[dst[i]], 1);
        return;
    }
    const int p = grp * 3 + role;                  // prep block index
    int i = p * 256 + threadIdx.x;
    if (i >= nitems) return;
    if (i < nx4) {
        float4 v = *(const float4*)&x[(size_t)i * 4];
        uint2 u;
        *(__half2*)&u.x = __floats2half2_rn(v.x, v.y);
        *(__half2*)&u.y = __floats2half2_rn(v.z, v.w);
        *(uint2*)&g_xh[(size_t)i * 4] = u;
        return;
    }
    int j = i - nx4;
    if (j < DIN * DHID) {
        int nn = j / DIN, k = j % DIN;
        g_W1t[j] = __float2half(W1[k * DHID + nn]);
        return;
    }
    j -= DIN * DHID;
    if (j < DIN * DFCH) {
        int nn = j / DIN, k = j % DIN;
        g_Wf1t[j] = __float2half(Wf1[k * DFCH + nn]);
        return;
    }
    j -= DIN * DFCH;
    if (j < DHID * DOUT) {
        int nn = j / DHID, k = j % DHID;
        g_W2t[j] = __float2half(W2[k * DOUT + nn]);
        return;
    }
    j -= DHID * DOUT;
    if (j < DFCH * DOUT) {
        int nn = j / DFCH, k = j % DFCH;
        g_Wf2t[j] = __float2half(Wf2[k * DOUT + nn]);
    }
}

// ---------------- single-kernel scan (flag-spin handshake) -------------------
// All nbl (<=256) blocks resident. Phase1: per-block inclusive scan -> bsum.
// Last arriving block scans block sums, sets flag. All blocks then emit
// rowptr/cursor/dinv and reset cnt. Counters self-reset for graph replay.
__global__ void scanall_k(int nbl, int n) {
    __shared__ int sm[256];
    __shared__ int lastBlk;
    const int t = threadIdx.x;
    const int i = blockIdx.x * 256 + t;
    const int v = (i < n) ? g_cnt[i] : 0;
    sm[t] = v;
    __syncthreads();
    for (int d = 1; d < 256; d <<= 1) {
        int a = (t >= d) ? sm[t - d] : 0;
        __syncthreads();
        sm[t] += a;
        __syncthreads();
    }
    const int incl = sm[t];
    if (t == 0) {
        g_bsum[blockIdx.x] = sm[255];
        __threadfence();
        lastBlk = (atomicAdd(&g_tick, 1) == nbl - 1);
    }
    __syncthreads();
    if (lastBlk) {
        __shared__ int sb[256];
        int bv = (t < nbl) ? g_bsum[t] : 0;
        sb[t] = bv;
        __syncthreads();
        for (int d = 1; d < 256; d <<= 1) {
            int a = (t >= d) ? sb[t - d] : 0;
            __syncthreads();
            sb[t] += a;
            __syncthreads();
        }
        if (t < nbl) g_bsum[t] = sb[t] - bv;     // exclusive
        if (t == 0) {
            g_rowptr[n] = sb[255];
            g_tick = 0;                           // reset for next replay
            __threadfence();
            atomicExch(&g_flag, 1);
        }
        __syncthreads();
    }
    if (t == 0) {
        while (atomicAdd(&g_flag, 0) == 0) {}
    }
    __syncthreads();
    __threadfence();
    if (i < n) {
        int excl = g_bsum[blockIdx.x] + incl - v;
        g_rowptr[i] = excl;
        g_cursor[i] = excl;
        g_dinv[i]   = rsqrtf((float)(v + 1));
        g_cnt[i]    = 0;                          // restore zeroed state
    }
    __syncthreads();
    if (t == 0) {
        if (atomicAdd(&g_done, 1) == nbl - 1) {   // last to finish resets
            g_done = 0;
            g_flag = 0;
        }
    }
}

// ---------------- mma / cp.async helpers ------------------------------------
__device__ __forceinline__ void mma_f16(float* d, const uint32_t* a, const uint32_t* b) {
    asm volatile(
        "mma.sync.aligned.m16n8k16.row.col.f32.f16.f16.f32 "
        "{%0,%1,%2,%3}, {%4,%5,%6,%7}, {%8,%9}, {%0,%1,%2,%3};"
        : "+f"(d[0]), "+f"(d[1]), "+f"(d[2]), "+f"(d[3])
        : "r"(a[0]), "r"(a[1]), "r"(a[2]), "r"(a[3]), "r"(b[0]), "r"(b[1]));
}

__device__ __forceinline__ uint32_t smem_u32(const void* p) {
    return (uint32_t)__cvta_generic_to_shared(p);
}
__device__ __forceinline__ void cpa16(uint32_t dst, const void* src, int sz) {
    asm volatile("cp.async.cg.shared.global [%0], [%1], 16, %2;"
                 :: "r"(dst), "l"(src), "r"(sz));
}
__device__ __forceinline__ void cpa_commit() {
    asm volatile("cp.async.commit_group;");
}
template <int NP>
__device__ __forceinline__ void cpa_wait() {
    asm volatile("cp.async.wait_group %0;" :: "n"(NP));
}

// ------------ fp16 mma core over one 32-k stage ------------------------------
template <int NT, int WT_STR>
__device__ __forceinline__ void mma_stage16(const __half* As, const __half* Wts,
                                            int kglob, float acc[2][NT][4],
                                            int lane, int warpM, int warpN) {
#pragma unroll
    for (int kk = 0; kk < 2; kk++) {
        const int kb = kk * 16;
        uint32_t a[2][4];
#pragma unroll
        for (int mt = 0; mt < 2; mt++) {
            const __half* Ap = &As[(warpM * 32 + mt * 16 + (lane >> 2)) * 40
                                   + kb + (lane & 3) * 2];
            a[mt][0] = *(const uint32_t*)Ap;
            a[mt][1] = *(const uint32_t*)(Ap + 8 * 40);
            a[mt][2] = *(const uint32_t*)(Ap + 8);
            a[mt][3] = *(const uint32_t*)(Ap + 8 * 40 + 8);
        }
#pragma unroll
        for (int nt = 0; nt < NT; nt++) {
            const int n0 = warpN * (NT * 8) + nt * 8 + (lane >> 2);
            const __half* Bp = &Wts[n0 * WT_STR + kglob + kb + (lane & 3) * 2];
            uint32_t b[2];
            b[0] = *(const uint32_t*)Bp;
            b[1] = *(const uint32_t*)(Bp + 8);
            mma_f16(acc[0][nt], a[0], b);
            mma_f16(acc[1][nt], a[1], b);
        }
    }
}

// ------------ epilogue: bias/relu/dinv-scale, fp16 store --------------------
template <int N, int NT, bool BIAS, bool RELU, bool SCALE>
__device__ __forceinline__ void gemm_epi(float acc[2][NT][4],
                                         const float* __restrict__ bias,
                                         __half* __restrict__ C, int nRows,
                                         int rowBase, int colBase,
                                         int lane, int warpM, int warpN) {
#pragma unroll
    for (int mt = 0; mt < 2; mt++) {
#pragma unroll
        for (int half = 0; half < 2; half++) {
            int row = rowBase + warpM * 32 + mt * 16 + (lane >> 2) + half * 8;
            if (row >= nRows) continue;
            float dsc = SCALE ? g_dinv[row] : 1.f;
#pragma unroll
            for (int nt = 0; nt < NT; nt++) {
                int col = colBase + warpN * (NT * 8) + nt * 8 + (lane & 3) * 2;
                float v0 = acc[mt][nt][half * 2 + 0];
                float v1 = acc[mt][nt][half * 2 + 1];
                if (BIAS) { v0 += bias[col]; v1 += bias[col + 1]; }
                if (RELU) { v0 = fmaxf(v0, 0.f); v1 = fmaxf(v1, 0.f); }
                if (SCALE) { v0 *= dsc; v1 *= dsc; }
                *(__half2*)&C[(size_t)row * N + col] = __floats2half2_rn(v0, v1);
            }
        }
    }
}

// ------------ pipelined fp16 GEMM (BN=128, Wt smem-resident, A cp.async) ----
template <int K, int N, bool BIAS, bool RELU, bool SCALE>
__device__ __forceinline__ void gemm16_pipe(const __half* __restrict__ A,
                                            const __half* __restrict__ Wt, // [N][K]
                                            const float* __restrict__ bias,
                                            __half* __restrict__ C, int nRows,
                                            int tileM, int colBase, char* smraw) {
    constexpr int BN = 128, NT = 8;
    constexpr int WT_STR = K + 8;
    __half* Wts = (__half*)smraw;
    __half* As0 = Wts + BN * WT_STR;
    __half* As1 = As0 + 128 * 40;
    __half* Asb[2] = {As0, As1};

    const int tid = threadIdx.x;
    const int lane = tid & 31;
    const int wid = tid >> 5;
    const int warpM = wid & 3;
    const int warpN = wid >> 2;
    const int rowBase = tileM * 128;

#pragma unroll
    for (int i = 0; i < BN * K / 8 / 256; i++) {
        int s = tid + i * 256;
        int row = s / (K / 8), c8 = s % (K / 8);
        cpa16(smem_u32(&Wts[row * WT_STR + c8 * 8]),
              &Wt[(size_t)(colBase + row) * K + c8 * 8], 16);
    }
    auto loadA = [&](int st, int k0) {
#pragma unroll
        for (int i = 0; i < 2; i++) {
            int s = tid + i * 256;
            int row = s >> 2, c8 = s & 3;
            int grow = rowBase + row;
            int ok = grow < nRows;
            cpa16(smem_u32(&Asb[st][row * 40 + c8 * 8]),
                  &A[(size_t)(ok ? grow : 0) * K + k0 + c8 * 8], ok ? 16 : 0);
        }
        cpa_commit();
    };

    float acc[2][NT][4];
#pragma unroll
    for (int mt = 0; mt < 2; mt++)
#pragma unroll
        for (int nt = 0; nt < NT; nt++)
#pragma unroll
            for (int i = 0; i < 4; i++) acc[mt][nt][i] = 0.f;

    loadA(0, 0);
    constexpr int NST = K / 32;
#pragma unroll
    for (int it = 0; it < NST; it++) {
        int st = it & 1;
        if (it + 1 < NST) loadA(st ^ 1, (it + 1) * 32);
        if (it + 1 < NST) cpa_wait<1>(); else cpa_wait<0>();
        __syncthreads();
        mma_stage16<NT, WT_STR>(Asb[st], Wts, it * 32, acc, lane, warpM, warpN);
        __syncthreads();
    }
    gemm_epi<N, NT, BIAS, RELU, SCALE>(acc, bias, C, nRows, rowBase, colBase,
                                       lane, warpM, warpN);
}

// ------------ synchronous fp16 GEMM (BN=64, per-stage loads) ----------------
template <int K, int N, bool BIAS, bool RELU, bool SCALE>
__device__ __forceinline__ void gemm16_sync(const __half* __restrict__ A,
                                            const __half* __restrict__ Wt, // [N][K]
                                            const float* __restrict__ bias,
                                            __half* __restrict__ C, int nRows,
                                            int tileM, __half* As, __half* Ws) {
    constexpr int NT = 4;
    const int tid = threadIdx.x;
    const int lane = tid & 31;
    const int wid = tid >> 5;
    const int warpM = wid & 3;
    const int warpN = wid >> 2;
    const int rowBase = tileM * 128;

    float acc[2][NT][4];
#pragma unroll
    for (int mt = 0; mt < 2; mt++)
#pragma unroll
        for (int nt = 0; nt < NT; nt++)
#pragma unroll
            for (int i = 0; i < 4; i++) acc[mt][nt][i] = 0.f;

    for (int k0 = 0; k0 < K; k0 += 32) {
#pragma unroll
        for (int i = 0; i < 2; i++) {
            int s = tid + i * 256;
            int row = s >> 2, c8 = s & 3;
            int grow = rowBase + row;
            uint4 v = make_uint4(0u, 0u, 0u, 0u);
            if (grow < nRows) v = *(const uint4*)&A[(size_t)grow * K + k0 + c8 * 8];
            *(uint4*)&As[row * 40 + c8 * 8] = v;
        }
        {
            int row = tid >> 2, c8 = tid & 3;
            *(uint4*)&Ws[row * 40 + c8 * 8] =
                *(const uint4*)&Wt[(size_t)row * K + k0 + c8 * 8];
        }
        __syncthreads();
        mma_stage16<NT, 40>(As, Ws, 0, acc, lane, warpM, warpN);
        __syncthreads();
    }
    gemm_epi<N, NT, BIAS, RELU, SCALE>(acc, bias, C, nRows, rowBase, 0,
                                       lane, warpM, warpN);
}

// ---------------- aggregation node body --------------------------------------
template <int F, bool RELU, bool COMBINE>
__device__ __forceinline__ void agg_node(int gw, const __half* __restrict__ H,
                                         const float* __restrict__ bias,
                                         const __half* __restrict__ FCh,
                                         __half* __restrict__ Out) {
    const int lane = threadIdx.x & 31;
    constexpr int FPT = F / 32;
    const int colb = lane * FPT;
    const float di = g_dinv[gw];

    float acc[FPT];
    if constexpr (FPT == 4) {
        uint2 u = *(const uint2*)&H[(size_t)gw * F + colb];
        float2 p0 = __half22float2(*(const __half2*)&u.x);
        float2 p1 = __half22float2(*(const __half2*)&u.y);
        acc[0] = p0.x; acc[1] = p0.y; acc[2] = p1.x; acc[3] = p1.y;
    } else {
        uint32_t u = *(const uint32_t*)&H[(size_t)gw * F + colb];
        float2 p = __half22float2(*(const __half2*)&u);
        acc[0] = p.x; acc[1] = p.y;
    }

    int e = g_rowptr[gw];
    const int end = g_rowptr[gw + 1];
    for (; e + 3 < end; e += 4) {
        int s0 = __ldg(&g_col[e + 0]);
        int s1 = __ldg(&g_col[e + 1]);
        int s2 = __ldg(&g_col[e + 2]);
        int s3 = __ldg(&g_col[e + 3]);
        if constexpr (FPT == 4) {
            uint2 u0 = *(const uint2*)&H[(size_t)s0 * F + colb];
            uint2 u1 = *(const uint2*)&H[(size_t)s1 * F + colb];
            uint2 u2 = *(const uint2*)&H[(size_t)s2 * F + colb];
            uint2 u3 = *(const uint2*)&H[(size_t)s3 * F + colb];
            float2 a0 = __half22float2(*(const __half2*)&u0.x);
            float2 a1 = __half22float2(*(const __half2*)&u0.y);
            float2 b0 = __half22float2(*(const __half2*)&u1.x);
            float2 b1 = __half22float2(*(const __half2*)&u1.y);
            float2 c0 = __half22float2(*(const __half2*)&u2.x);
            float2 c1 = __half22float2(*(const __half2*)&u2.y);
            float2 d0 = __half22float2(*(const __half2*)&u3.x);
            float2 d1 = __half22float2(*(const __half2*)&u3.y);
            acc[0] += (a0.x + b0.x) + (c0.x + d0.x);
            acc[1] += (a0.y + b0.y) + (c0.y + d0.y);
            acc[2] += (a1.x + b1.x) + (c1.x + d1.x);
            acc[3] += (a1.y + b1.y) + (c1.y + d1.y);
        } else {
            uint32_t u0 = *(const uint32_t*)&H[(size_t)s0 * F + colb];
            uint32_t u1 = *(const uint32_t*)&H[(size_t)s1 * F + colb];
            uint32_t u2 = *(const uint32_t*)&H[(size_t)s2 * F + colb];
            uint32_t u3 = *(const uint32_t*)&H[(size_t)s3 * F + colb];
            float2 a = __half22float2(*(const __half2*)&u0);
            float2 b = __half22float2(*(const __half2*)&u1);
            float2 c = __half22float2(*(const __half2*)&u2);
            float2 d = __half22float2(*(const __half2*)&u3);
            acc[0] += (a.x + b.x) + (c.x + d.x);
            acc[1] += (a.y + b.y) + (c.y + d.y);
        }
    }
    for (; e < end; e++) {
        int s0 = __ldg(&g_col[e]);
        if constexpr (FPT == 4) {
            uint2 u0 = *(const uint2*)&H[(size_t)s0 * F + colb];
            float2 a0 = __half22float2(*(const __half2*)&u0.x);
            float2 a1 = __half22float2(*(const __half2*)&u0.y);
            acc[0] += a0.x; acc[1] += a0.y;
            acc[2] += a1.x; acc[3] += a1.y;
        } else {
            uint32_t u0 = *(const uint32_t*)&H[(size_t)s0 * F + colb];
            float2 a = __half22float2(*(const __half2*)&u0);
            acc[0] += a.x; acc[1] += a.y;
        }
    }

    float fc[FPT];
    if constexpr (COMBINE) {
        if constexpr (FPT == 2) {
            float2 f = __half22float2(*(const __half2*)&FCh[(size_t)gw * F + colb]);
            fc[0] = f.x; fc[1] = f.y;
        } else {
            uint2 u = *(const uint2*)&FCh[(size_t)gw * F + colb];
            float2 f0 = __half22float2(*(const __half2*)&u.x);
            float2 f1 = __half22float2(*(const __half2*)&u.y);
            fc[0] = f0.x; fc[1] = f0.y; fc[2] = f1.x; fc[3] = f1.y;
        }
    }

#pragma unroll
    for (int j = 0; j < FPT; j++) {
        float o = di * acc[j] + bias[colb + j];
        if (RELU) o = fmaxf(o, 0.f);
        if (COMBINE) o = 0.5f * o + 0.5f * fc[j];
        acc[j] = o;
    }
    if constexpr (FPT == 4) {
        uint2 u;
        *(__half2*)&u.x = __floats2half2_rn(acc[0], acc[1]);
        *(__half2*)&u.y = __floats2half2_rn(acc[2], acc[3]);
        *(uint2*)&Out[(size_t)gw * F + colb] = u;
    } else {
        *(__half2*)&Out[(size_t)gw * F + colb] = __floats2half2_rn(acc[0], acc[1]);
    }
}

// ---- fused: F1 + H1 GEMM tiles (3 of 4 blocks) || CSR-fill (1 of 4) --------
__global__ void __launch_bounds__(256, 2) gemmfill_k(const float* __restrict__ bf1,
                                                     const int* __restrict__ ei,
                                                     int ne, int mb, int n) {
    extern __shared__ char dyn_sm[];
    const int role = blockIdx.x & 3;
    const int grp  = blockIdx.x >> 2;
    if (role == 3) {                               // fill chunk
        const int nch = gridDim.x >> 2;
        const int per = (ne + nch - 1) / nch;
        const int s = grp * per;
        const int e = min(s + per, ne);
        for (int i = s + (int)threadIdx.x; i < e; i += 256) {
            int sv = ei[i];
            int dv = ei[ne + i];
            g_col[atomicAdd(&g_cursor[dv], 1)] = sv;
        }
        return;
    }
    const int idx = grp * 3 + role;                // 0 .. 3*mb-1
    if (idx < 2 * mb) {
        gemm16_pipe<DIN, DFCH, true, true, false>(g_xh, g_Wf1t, bf1, g_F1h, n,
                                                  idx % mb, (idx / mb) * 128, dyn_sm);
    } else {
        gemm16_pipe<DIN, DHID, false, false, true>(g_xh, g_W1t, nullptr, g_H1h, n,
                                                   idx - 2 * mb, 0, dyn_sm);
    }
}

// ---- fused: agg1 (15 of 16 blocks) || FC GEMM tiles (1 of 16) --------------
__global__ void __launch_bounds__(256) aggfc_k(const float* __restrict__ b1,
                                               const float* __restrict__ bf2,
                                               int n, int mb) {
    __shared__ __half smem[128 * 40 + 64 * 40];
    const int local = blockIdx.x & 15;
    const int grp = blockIdx.x >> 4;
    if (local == 15) {                             // FC GEMM tile
        if (grp >= mb) return;
        gemm16_sync<DFCH, DOUT, true, false, false>(g_F1h, g_Wf2t, bf2, g_FCh, n,
                                                    grp, smem, smem + 128 * 40);
        return;
    }
    const int aggIdx = grp * 15 + local;
    const int gw = aggIdx * 8 + ((int)threadIdx.x >> 5);
    if (gw >= n) return;
    agg_node<DHID, true, false>(gw, g_H1h, b1, nullptr, g_A1h);
}

// ---- GEMM: H2' = dinv * (A1 @ W2) ------------------------------------------
__global__ void __launch_bounds__(256) gemmh2_k(int n) {
    __shared__ __half smem[128 * 40 + 64 * 40];
    gemm16_sync<DHID, DOUT, false, false, true>(g_A1h, g_W2t, nullptr, g_H2h, n,
                                                blockIdx.x, smem, smem + 128 * 40);
}

// ---- agg2 + combine: z = 0.5*(agg(H2')+b2) + 0.5*FC -------------------------
__global__ void __launch_bounds__(256) agg2z_k(const float* __restrict__ b2, int n) {
    const int gw = (blockIdx.x * 256 + threadIdx.x) >> 5;
    if (gw >= n) return;
    agg_node<DOUT, false, true>(gw, g_H2h, b2, g_FCh, g_Zh);
}

// ---------------- decode (fp16 z): 8 lanes/query, uint4 loads ---------------
__global__ void __launch_bounds__(256) decodeh_k(const int* __restrict__ eli,
                                                 float* __restrict__ out, int nq) {
    int t = blockIdx.x * 256 + threadIdx.x;
    int q = t >> 3;
    int l = t & 7;
    if (q >= nq) return;
    int a = eli[q];
    int b = eli[nq + q];
    uint4 ua = *(const uint4*)&g_Zh[(size_t)a * DOUT + l * 8];
    uint4 ub = *(const uint4*)&g_Zh[(size_t)b * DOUT + l * 8];
    float2 a0 = __half22float2(*(const __half2*)&ua.x);
    float2 a1 = __half22float2(*(const __half2*)&ua.y);
    float2 a2 = __half22float2(*(const __half2*)&ua.z);
    float2 a3 = __half22float2(*(const __half2*)&ua.w);
    float2 b0 = __half22float2(*(const __half2*)&ub.x);
    float2 b1 = __half22float2(*(const __half2*)&ub.y);
    float2 b2 = __half22float2(*(const __half2*)&ub.z);
    float2 b3 = __half22float2(*(const __half2*)&ub.w);
    float p = a0.x * b0.x + a0.y * b0.y + a1.x * b1.x + a1.y * b1.y
            + a2.x * b2.x + a2.y * b2.y + a3.x * b3.x + a3.y * b3.y;
    p += __shfl_xor_sync(0xffffffffu, p, 4);
    p += __shfl_xor_sync(0xffffffffu, p, 2);
    p += __shfl_xor_sync(0xffffffffu, p, 1);
    if (l == 0) out[q] = p;
}

// ---------------- launch ----------------------------------------------------
extern "C" void kernel_launch(void* const* d_in, const int* in_sizes, int n_in,
                              void* d_out, int out_size) {
    const float* x   = (const float*)d_in[0];
    const int*   ei  = (const int*)d_in[1];
    const int*   eli = (const int*)d_in[2];
    const float* W1  = (const float*)d_in[3];
    const float* b1  = (const float*)d_in[4];
    const float* W2  = (const float*)d_in[5];
    const float* b2  = (const float*)d_in[6];
    const float* Wf1 = (const float*)d_in[7];
    const float* bf1 = (const float*)d_in[8];
    const float* Wf2 = (const float*)d_in[9];
    const float* bf2 = (const float*)d_in[10];
    float* out = (float*)d_out;

    const int n  = in_sizes[0] / DIN;
    const int ne = in_sizes[1] / 2;
    const int nq = in_sizes[2] / 2;

    const int PIPE_SMEM = (128 * 136 + 2 * 128 * 40) * 2;   // 55296 B
    cudaFuncSetAttribute(gemmfill_k, cudaFuncAttributeMaxDynamicSharedMemorySize, PIPE_SMEM);

    const int mb = (n + 127) / 128;                 // GEMM row tiles (391)
    const int nb = (n + 255) / 256;                 // scan blocks (196, <=256)
    const int aggBlocks = (n * 32 + 255) / 256;     // warp-per-node blocks
    const int nx4 = (n * DIN) / 4;
    const int wtot = DIN * DHID + DIN * DFCH + DHID * DOUT + DFCH * DOUT;
    const int nitems = nx4 + wtot;

    // 1. [prep (x->fp16, weights->fp16^T) || histogram]  (g_cnt arrives zeroed)
    const int pgrp = (nitems + 767) / 768;
    prephist_k<<<4 * pgrp, 256>>>(x, W1, Wf1, W2, Wf2, ei + ne, nx4, nitems, ne);
    // 2. single-kernel scan -> rowptr, cursor, dinv (+ cnt reset)
    scanall_k<<<nb, 256>>>(nb, n);
    // 3. [F1 GEMM + H1 GEMM (dinv-scaled) || CSR fill]
    gemmfill_k<<<4 * mb, 256, PIPE_SMEM>>>(bf1, ei, ne, mb, n);
    // 4. [agg1 -> A1 || FC GEMM -> FC]
    const int agrp = (aggBlocks + 14) / 15;
    aggfc_k<<<16 * agrp, 256>>>(b1, bf2, n, mb);
    // 5. H2' = dinv * (A1 @ W2)
    gemmh2_k<<<mb, 256>>>(n);
    // 6. z = 0.5*(agg(H2')+b2) + 0.5*FC
    agg2z_k<<<aggBlocks, 256>>>(b2, n);
    // 7. edge dot-product decode
    decodeh_k<<<(nq * 8 + 255) / 256, 256>>>(eli, out, nq);
}

// round 15
// speedup vs baseline: 1.3659x; 1.0430x over previous
#include <cuda_runtime.h>
#include <cuda_fp16.h>
#include <math.h>
#include <stdint.h>

// Problem constants (fixed by the dataset)
#define NN   50000
#define NE   1600000
#define DIN  128
#define DHID 128
#define DOUT 64
#define DFCH 256

// ---------------- scratch (device globals; no allocation allowed) ----------
static __device__ __align__(16) __half g_xh [NN * DIN];   // x, fp16
static __device__ __align__(16) __half g_H1h[NN * DHID];  // dinv * (x @ W1), fp16
static __device__ __align__(16) __half g_A1h[NN * DHID];  // relu(agg1 + b1), fp16
static __device__ __align__(16) __half g_H2h[NN * DOUT];  // dinv * (A1 @ W2), fp16
static __device__ __align__(16) __half g_F1h[NN * DFCH];  // relu(x@Wf1+bf1), fp16
static __device__ __align__(16) __half g_FCh[NN * DOUT];  // F1@Wf2+bf2, fp16
static __device__ __align__(16) __half g_Zh[NN * DOUT];   // 0.5*gcn + 0.5*fc, fp16
// fp16 transposed weights: Wt[n][k]
static __device__ __align__(16) __half g_W1t [DHID * DIN];
static __device__ __align__(16) __half g_Wf1t[DFCH * DIN];
static __device__ __align__(16) __half g_W2t [DOUT * DHID];
static __device__ __align__(16) __half g_Wf2t[DOUT * DFCH];
static __device__ int   g_cnt[NN];                        // zero at rest
static __device__ int   g_rowptr[NN + 1];
static __device__ int   g_cursor[NN];
static __device__ int   g_col[NE];
static __device__ float g_dinv[NN];
static __device__ int   g_bsum[256];
static __device__ int   g_tick;                           // zero at rest
static __device__ int   g_flag;                           // zero at rest
static __device__ int   g_done;                           // zero at rest

// ---------------- fused prep (x->fp16, weights->fp16^T) || histogram --------
__global__ void prephist_k(const float* __restrict__ x,
                           const float* __restrict__ W1, const float* __restrict__ Wf1,
                           const float* __restrict__ W2, const float* __restrict__ Wf2,
                           const int* __restrict__ dst,
                           int nx4, int nitems, int ne) {
    const int role = blockIdx.x & 3;
    const int grp  = blockIdx.x >> 2;
    if (role == 3) {                               // histogram chunk
        const int nch = gridDim.x >> 2;
        const int per = (ne + nch - 1) / nch;
        const int s = grp * per;
        const int e = min(s + per, ne);
        for (int i = s + (int)threadIdx.x; i < e; i += 256)
            atomicAdd(&g_cnt[dst[i]], 1);
        return;
    }
    const int p = grp * 3 + role;                  // prep block index
    int i = p * 256 + threadIdx.x;
    if (i >= nitems) return;
    if (i < nx4) {
        float4 v = *(const float4*)&x[(size_t)i * 4];
        uint2 u;
        *(__half2*)&u.x = __floats2half2_rn(v.x, v.y);
        *(__half2*)&u.y = __floats2half2_rn(v.z, v.w);
        *(uint2*)&g_xh[(size_t)i * 4] = u;
        return;
    }
    int j = i - nx4;
    if (j < DIN * DHID) {
        int nn = j / DIN, k = j % DIN;
        g_W1t[j] = __float2half(W1[k * DHID + nn]);
        return;
    }
    j -= DIN * DHID;
    if (j < DIN * DFCH) {
        int nn = j / DIN, k = j % DIN;
        g_Wf1t[j] = __float2half(Wf1[k * DFCH + nn]);
        return;
    }
    j -= DIN * DFCH;
    if (j < DHID * DOUT) {
        int nn = j / DHID, k = j % DHID;
        g_W2t[j] = __float2half(W2[k * DOUT + nn]);
        return;
    }
    j -= DHID * DOUT;
    if (j < DFCH * DOUT) {
        int nn = j / DFCH, k = j % DFCH;
        g_Wf2t[j] = __float2half(Wf2[k * DOUT + nn]);
    }
}

// ---------------- single-kernel scan (flag-spin handshake) -------------------
__global__ void scanall_k(int nbl, int n) {
    __shared__ int sm[256];
    __shared__ int lastBlk;
    const int t = threadIdx.x;
    const int i = blockIdx.x * 256 + t;
    const int v = (i < n) ? g_cnt[i] : 0;
    sm[t] = v;
    __syncthreads();
    for (int d = 1; d < 256; d <<= 1) {
        int a = (t >= d) ? sm[t - d] : 0;
        __syncthreads();
        sm[t] += a;
        __syncthreads();
    }
    const int incl = sm[t];
    if (t == 0) {
        g_bsum[blockIdx.x] = sm[255];
        __threadfence();
        lastBlk = (atomicAdd(&g_tick, 1) == nbl - 1);
    }
    __syncthreads();
    if (lastBlk) {
        __shared__ int sb[256];
        int bv = (t < nbl) ? g_bsum[t] : 0;
        sb[t] = bv;
        __syncthreads();
        for (int d = 1; d < 256; d <<= 1) {
            int a = (t >= d) ? sb[t - d] : 0;
            __syncthreads();
            sb[t] += a;
            __syncthreads();
        }
        if (t < nbl) g_bsum[t] = sb[t] - bv;     // exclusive
        if (t == 0) {
            g_rowptr[n] = sb[255];
            g_tick = 0;
            __threadfence();
            atomicExch(&g_flag, 1);
        }
        __syncthreads();
    }
    if (t == 0) {
        while (atomicAdd(&g_flag, 0) == 0) {}
    }
    __syncthreads();
    __threadfence();
    if (i < n) {
        int excl = g_bsum[blockIdx.x] + incl - v;
        g_rowptr[i] = excl;
        g_cursor[i] = excl;
        g_dinv[i]   = rsqrtf((float)(v + 1));
        g_cnt[i]    = 0;
    }
    __syncthreads();
    if (t == 0) {
        if (atomicAdd(&g_done, 1) == nbl - 1) {
            g_done = 0;
            g_flag = 0;
        }
    }
}

// ---------------- mma / cp.async helpers ------------------------------------
__device__ __forceinline__ void mma_f16(float* d, const uint32_t* a, const uint32_t* b) {
    asm volatile(
        "mma.sync.aligned.m16n8k16.row.col.f32.f16.f16.f32 "
        "{%0,%1,%2,%3}, {%4,%5,%6,%7}, {%8,%9}, {%0,%1,%2,%3};"
        : "+f"(d[0]), "+f"(d[1]), "+f"(d[2]), "+f"(d[3])
        : "r"(a[0]), "r"(a[1]), "r"(a[2]), "r"(a[3]), "r"(b[0]), "r"(b[1]));
}

__device__ __forceinline__ uint32_t smem_u32(const void* p) {
    return (uint32_t)__cvta_generic_to_shared(p);
}
__device__ __forceinline__ void cpa16(uint32_t dst, const void* src, int sz) {
    asm volatile("cp.async.cg.shared.global [%0], [%1], 16, %2;"
                 :: "r"(dst), "l"(src), "r"(sz));
}
__device__ __forceinline__ void cpa_commit() {
    asm volatile("cp.async.commit_group;");
}
template <int NP>
__device__ __forceinline__ void cpa_wait() {
    asm volatile("cp.async.wait_group %0;" :: "n"(NP));
}

// ------------ fp16 mma core over one 32-k stage ------------------------------
template <int NT, int WT_STR>
__device__ __forceinline__ void mma_stage16(const __half* As, const __half* Wts,
                                            int kglob, float acc[2][NT][4],
                                            int lane, int warpM, int warpN) {
#pragma unroll
    for (int kk = 0; kk < 2; kk++) {
        const int kb = kk * 16;
        uint32_t a[2][4];
#pragma unroll
        for (int mt = 0; mt < 2; mt++) {
            const __half* Ap = &As[(warpM * 32 + mt * 16 + (lane >> 2)) * 40
                                   + kb + (lane & 3) * 2];
            a[mt][0] = *(const uint32_t*)Ap;
            a[mt][1] = *(const uint32_t*)(Ap + 8 * 40);
            a[mt][2] = *(const uint32_t*)(Ap + 8);
            a[mt][3] = *(const uint32_t*)(Ap + 8 * 40 + 8);
        }
#pragma unroll
        for (int nt = 0; nt < NT; nt++) {
            const int n0 = warpN * (NT * 8) + nt * 8 + (lane >> 2);
            const __half* Bp = &Wts[n0 * WT_STR + kglob + kb + (lane & 3) * 2];
            uint32_t b[2];
            b[0] = *(const uint32_t*)Bp;
            b[1] = *(const uint32_t*)(Bp + 8);
            mma_f16(acc[0][nt], a[0], b);
            mma_f16(acc[1][nt], a[1], b);
        }
    }
}

// ------------ epilogue: bias/relu/dinv-scale, fp16 store --------------------
template <int N, int NT, bool BIAS, bool RELU, bool SCALE>
__device__ __forceinline__ void gemm_epi(float acc[2][NT][4],
                                         const float* __restrict__ bias,
                                         __half* __restrict__ C, int nRows,
                                         int rowBase, int colBase,
                                         int lane, int warpM, int warpN) {
#pragma unroll
    for (int mt = 0; mt < 2; mt++) {
#pragma unroll
        for (int half = 0; half < 2; half++) {
            int row = rowBase + warpM * 32 + mt * 16 + (lane >> 2) + half * 8;
            if (row >= nRows) continue;
            float dsc = SCALE ? g_dinv[row] : 1.f;
#pragma unroll
            for (int nt = 0; nt < NT; nt++) {
                int col = colBase + warpN * (NT * 8) + nt * 8 + (lane & 3) * 2;
                float v0 = acc[mt][nt][half * 2 + 0];
                float v1 = acc[mt][nt][half * 2 + 1];
                if (BIAS) { v0 += bias[col]; v1 += bias[col + 1]; }
                if (RELU) { v0 = fmaxf(v0, 0.f); v1 = fmaxf(v1, 0.f); }
                if (SCALE) { v0 *= dsc; v1 *= dsc; }
                *(__half2*)&C[(size_t)row * N + col] = __floats2half2_rn(v0, v1);
            }
        }
    }
}

// ------------ pipelined fp16 GEMM (BN=128, Wt smem-resident, A cp.async) ----
template <int K, int N, bool BIAS, bool RELU, bool SCALE>
__device__ __forceinline__ void gemm16_pipe(const __half* __restrict__ A,
                                            const __half* __restrict__ Wt, // [N][K]
                                            const float* __restrict__ bias,
                                            __half* __restrict__ C, int nRows,
                                            int tileM, int colBase, char* smraw) {
    constexpr int BN = 128, NT = 8;
    constexpr int WT_STR = K + 8;
    __half* Wts = (__half*)smraw;
    __half* As0 = Wts + BN * WT_STR;
    __half* As1 = As0 + 128 * 40;
    __half* Asb[2] = {As0, As1};

    const int tid = threadIdx.x;
    const int lane = tid & 31;
    const int wid = tid >> 5;
    const int warpM = wid & 3;
    const int warpN = wid >> 2;
    const int rowBase = tileM * 128;

#pragma unroll
    for (int i = 0; i < BN * K / 8 / 256; i++) {
        int s = tid + i * 256;
        int row = s / (K / 8), c8 = s % (K / 8);
        cpa16(smem_u32(&Wts[row * WT_STR + c8 * 8]),
              &Wt[(size_t)(colBase + row) * K + c8 * 8], 16);
    }
    auto loadA = [&](int st, int k0) {
#pragma unroll
        for (int i = 0; i < 2; i++) {
            int s = tid + i * 256;
            int row = s >> 2, c8 = s & 3;
            int grow = rowBase + row;
            int ok = grow < nRows;
            cpa16(smem_u32(&Asb[st][row * 40 + c8 * 8]),
                  &A[(size_t)(ok ? grow : 0) * K + k0 + c8 * 8], ok ? 16 : 0);
        }
        cpa_commit();
    };

    float acc[2][NT][4];
#pragma unroll
    for (int mt = 0; mt < 2; mt++)
#pragma unroll
        for (int nt = 0; nt < NT; nt++)
#pragma unroll
            for (int i = 0; i < 4; i++) acc[mt][nt][i] = 0.f;

    loadA(0, 0);
    constexpr int NST = K / 32;
#pragma unroll
    for (int it = 0; it < NST; it++) {
        int st = it & 1;
        if (it + 1 < NST) loadA(st ^ 1, (it + 1) * 32);
        if (it + 1 < NST) cpa_wait<1>(); else cpa_wait<0>();
        __syncthreads();
        mma_stage16<NT, WT_STR>(Asb[st], Wts, it * 32, acc, lane, warpM, warpN);
        __syncthreads();
    }
    gemm_epi<N, NT, BIAS, RELU, SCALE>(acc, bias, C, nRows, rowBase, colBase,
                                       lane, warpM, warpN);
}

// ------------ synchronous fp16 GEMM (BN=64, per-stage loads) ----------------
template <int K, int N, bool BIAS, bool RELU, bool SCALE>
__device__ __forceinline__ void gemm16_sync(const __half* __restrict__ A,
                                            const __half* __restrict__ Wt, // [N][K]
                                            const float* __restrict__ bias,
                                            __half* __restrict__ C, int nRows,
                                            int tileM, __half* As, __half* Ws) {
    constexpr int NT = 4;
    const int tid = threadIdx.x;
    const int lane = tid & 31;
    const int wid = tid >> 5;
    const int warpM = wid & 3;
    const int warpN = wid >> 2;
    const int rowBase = tileM * 128;

    float acc[2][NT][4];
#pragma unroll
    for (int mt = 0; mt < 2; mt++)
#pragma unroll
        for (int nt = 0; nt < NT; nt++)
#pragma unroll
            for (int i = 0; i < 4; i++) acc[mt][nt][i] = 0.f;

    for (int k0 = 0; k0 < K; k0 += 32) {
#pragma unroll
        for (int i = 0; i < 2; i++) {
            int s = tid + i * 256;
            int row = s >> 2, c8 = s & 3;
            int grow = rowBase + row;
            uint4 v = make_uint4(0u, 0u, 0u, 0u);
            if (grow < nRows) v = *(const uint4*)&A[(size_t)grow * K + k0 + c8 * 8];
            *(uint4*)&As[row * 40 + c8 * 8] = v;
        }
        {
            int row = tid >> 2, c8 = tid & 3;
            *(uint4*)&Ws[row * 40 + c8 * 8] =
                *(const uint4*)&Wt[(size_t)row * K + k0 + c8 * 8];
        }
        __syncthreads();
        mma_stage16<NT, 40>(As, Ws, 0, acc, lane, warpM, warpN);
        __syncthreads();
    }
    gemm_epi<N, NT, BIAS, RELU, SCALE>(acc, bias, C, nRows, rowBase, 0,
                                       lane, warpM, warpN);
}

// ---------------- aggregation node body --------------------------------------
// H PRESCALED by dinv. Gather-sum with fp16 pairwise tree (HADD2) to halve
// convert+add instruction count; pair sums promoted to fp32 accumulators.
template <int F, bool RELU, bool COMBINE>
__device__ __forceinline__ void agg_node(int gw, const __half* __restrict__ H,
                                         const float* __restrict__ bias,
                                         const __half* __restrict__ FCh,
                                         __half* __restrict__ Out) {
    const int lane = threadIdx.x & 31;
    constexpr int FPT = F / 32;
    const int colb = lane * FPT;
    const float di = g_dinv[gw];

    float acc[FPT];
    if constexpr (FPT == 4) {
        uint2 u = *(const uint2*)&H[(size_t)gw * F + colb];
        float2 p0 = __half22float2(*(const __half2*)&u.x);
        float2 p1 = __half22float2(*(const __half2*)&u.y);
        acc[0] = p0.x; acc[1] = p0.y; acc[2] = p1.x; acc[3] = p1.y;
    } else {
        uint32_t u = *(const uint32_t*)&H[(size_t)gw * F + colb];
        float2 p = __half22float2(*(const __half2*)&u);
        acc[0] = p.x; acc[1] = p.y;
    }

    int e = g_rowptr[gw];
    const int end = g_rowptr[gw + 1];
    for (; e + 3 < end; e += 4) {
        int s0 = __ldg(&g_col[e + 0]);
        int s1 = __ldg(&g_col[e + 1]);
        int s2 = __ldg(&g_col[e + 2]);
        int s3 = __ldg(&g_col[e + 3]);
        if constexpr (FPT == 4) {
            uint2 u0 = *(const uint2*)&H[(size_t)s0 * F + colb];
            uint2 u1 = *(const uint2*)&H[(size_t)s1 * F + colb];
            uint2 u2 = *(const uint2*)&H[(size_t)s2 * F + colb];
            uint2 u3 = *(const uint2*)&H[(size_t)s3 * F + colb];
            // fp16 pairwise tree: one HADD2 depth, then fp32
            __half2 t0 = __hadd2(*(const __half2*)&u0.x, *(const __half2*)&u1.x);
            __half2 t1 = __hadd2(*(const __half2*)&u0.y, *(const __half2*)&u1.y);
            __half2 t2 = __hadd2(*(const __half2*)&u2.x, *(const __half2*)&u3.x);
            __half2 t3 = __hadd2(*(const __half2*)&u2.y, *(const __half2*)&u3.y);
            float2 f0 = __half22float2(t0);
            float2 f1 = __half22float2(t1);
            float2 f2 = __half22float2(t2);
            float2 f3 = __half22float2(t3);
            acc[0] += f0.x + f2.x;
            acc[1] += f0.y + f2.y;
            acc[2] += f1.x + f3.x;
            acc[3] += f1.y + f3.y;
        } else {
            uint32_t u0 = *(const uint32_t*)&H[(size_t)s0 * F + colb];
            uint32_t u1 = *(const uint32_t*)&H[(size_t)s1 * F + colb];
            uint32_t u2 = *(const uint32_t*)&H[(size_t)s2 * F + colb];
            uint32_t u3 = *(const uint32_t*)&H[(size_t)s3 * F + colb];
            __half2 t01 = __hadd2(*(const __half2*)&u0, *(const __half2*)&u1);
            __half2 t23 = __hadd2(*(const __half2*)&u2, *(const __half2*)&u3);
            float2 f01 = __half22float2(t01);
            float2 f23 = __half22float2(t23);
            acc[0] += f01.x + f23.x;
            acc[1] += f01.y + f23.y;
        }
    }
    for (; e < end; e++) {
        int s0 = __ldg(&g_col[e]);
        if constexpr (FPT == 4) {
            uint2 u0 = *(const uint2*)&H[(size_t)s0 * F + colb];
            float2 a0 = __half22float2(*(const __half2*)&u0.x);
            float2 a1 = __half22float2(*(const __half2*)&u0.y);
            acc[0] += a0.x; acc[1] += a0.y;
            acc[2] += a1.x; acc[3] += a1.y;
        } else {
            uint32_t u0 = *(const uint32_t*)&H[(size_t)s0 * F + colb];
            float2 a = __half22float2(*(const __half2*)&u0);
            acc[0] += a.x; acc[1] += a.y;
        }
    }

    float fc[FPT];
    if constexpr (COMBINE) {
        if constexpr (FPT == 2) {
            float2 f = __half22float2(*(const __half2*)&FCh[(size_t)gw * F + colb]);
            fc[0] = f.x; fc[1] = f.y;
        } else {
            uint2 u = *(const uint2*)&FCh[(size_t)gw * F + colb];
            float2 f0 = __half22float2(*(const __half2*)&u.x);
            float2 f1 = __half22float2(*(const __half2*)&u.y);
            fc[0] = f0.x; fc[1] = f0.y; fc[2] = f1.x; fc[3] = f1.y;
        }
    }

#pragma unroll
    for (int j = 0; j < FPT; j++) {
        float o = di * acc[j] + bias[colb + j];
        if (RELU) o = fmaxf(o, 0.f);
        if (COMBINE) o = 0.5f * o + 0.5f * fc[j];
        acc[j] = o;
    }
    if constexpr (FPT == 4) {
        uint2 u;
        *(__half2*)&u.x = __floats2half2_rn(acc[0], acc[1]);
        *(__half2*)&u.y = __floats2half2_rn(acc[2], acc[3]);
        *(uint2*)&Out[(size_t)gw * F + colb] = u;
    } else {
        *(__half2*)&Out[(size_t)gw * F + colb] = __floats2half2_rn(acc[0], acc[1]);
    }
}

// ---- fused: F1 + H1 GEMM tiles (3 of 4 blocks) || CSR-fill (1 of 4) --------
__global__ void __launch_bounds__(256, 2) gemmfill_k(const float* __restrict__ bf1,
                                                     const int* __restrict__ ei,
                                                     int ne, int mb, int n) {
    extern __shared__ char dyn_sm[];
    const int role = blockIdx.x & 3;
    const int grp  = blockIdx.x >> 2;
    if (role == 3) {                               // fill chunk
        const int nch = gridDim.x >> 2;
        const int per = (ne + nch - 1) / nch;
        const int s = grp * per;
        const int e = min(s + per, ne);
        for (int i = s + (int)threadIdx.x; i < e; i += 256) {
            int sv = ei[i];
            int dv = ei[ne + i];
            g_col[atomicAdd(&g_cursor[dv], 1)] = sv;
        }
        return;
    }
    const int idx = grp * 3 + role;                // 0 .. 3*mb-1
    if (idx < 2 * mb) {
        gemm16_pipe<DIN, DFCH, true, true, false>(g_xh, g_Wf1t, bf1, g_F1h, n,
                                                  idx % mb, (idx / mb) * 128, dyn_sm);
    } else {
        gemm16_pipe<DIN, DHID, false, false, true>(g_xh, g_W1t, nullptr, g_H1h, n,
                                                   idx - 2 * mb, 0, dyn_sm);
    }
}

// ---- pure agg1 (no smem, low regs -> high occupancy) ------------------------
__global__ void __launch_bounds__(256) agg1_k(const float* __restrict__ b1, int n) {
    const int gw = (blockIdx.x * 256 + threadIdx.x) >> 5;
    if (gw >= n) return;
    agg_node<DHID, true, false>(gw, g_H1h, b1, nullptr, g_A1h);
}

// ---- striped: H2' = dinv*(A1@W2) (even) || FC = F1@Wf2+bf2 (odd) -----------
__global__ void __launch_bounds__(256) gemmh2fc_k(const float* __restrict__ bf2,
                                                  int n, int mb) {
    __shared__ __half smem[128 * 40 + 64 * 40];
    const int role = blockIdx.x & 1;
    const int tile = blockIdx.x >> 1;
    if (tile >= mb) return;
    if (role == 0) {
        gemm16_sync<DHID, DOUT, false, false, true>(g_A1h, g_W2t, nullptr, g_H2h, n,
                                                    tile, smem, smem + 128 * 40);
    } else {
        gemm16_sync<DFCH, DOUT, true, false, false>(g_F1h, g_Wf2t, bf2, g_FCh, n,
                                                    tile, smem, smem + 128 * 40);
    }
}

// ---- agg2 + combine: z = 0.5*(agg(H2')+b2) + 0.5*FC -------------------------
__global__ void __launch_bounds__(256) agg2z_k(const float* __restrict__ b2, int n) {
    const int gw = (blockIdx.x * 256 + threadIdx.x) >> 5;
    if (gw >= n) return;
    agg_node<DOUT, false, true>(gw, g_H2h, b2, g_FCh, g_Zh);
}

// ---------------- decode (fp16 z): 8 lanes/query, uint4 loads ---------------
__global__ void __launch_bounds__(256) decodeh_k(const int* __restrict__ eli,
                                                 float* __restrict__ out, int nq) {
    int t = blockIdx.x * 256 + threadIdx.x;
    int q = t >> 3;
    int l = t & 7;
    if (q >= nq) return;
    int a = eli[q];
    int b = eli[nq + q];
    uint4 ua = *(const uint4*)&g_Zh[(size_t)a * DOUT + l * 8];
    uint4 ub = *(const uint4*)&g_Zh[(size_t)b * DOUT + l * 8];
    float2 a0 = __half22float2(*(const __half2*)&ua.x);
    float2 a1 = __half22float2(*(const __half2*)&ua.y);
    float2 a2 = __half22float2(*(const __half2*)&ua.z);
    float2 a3 = __half22float2(*(const __half2*)&ua.w);
    float2 b0 = __half22float2(*(const __half2*)&ub.x);
    float2 b1 = __half22float2(*(const __half2*)&ub.y);
    float2 b2 = __half22float2(*(const __half2*)&ub.z);
    float2 b3 = __half22float2(*(const __half2*)&ub.w);
    float p = a0.x * b0.x + a0.y * b0.y + a1.x * b1.x + a1.y * b1.y
            + a2.x * b2.x + a2.y * b2.y + a3.x * b3.x + a3.y * b3.y;
    p += __shfl_xor_sync(0xffffffffu, p, 4);
    p += __shfl_xor_sync(0xffffffffu, p, 2);
    p += __shfl_xor_sync(0xffffffffu, p, 1);
    if (l == 0) out[q] = p;
}

// ---------------- launch ----------------------------------------------------
extern "C" void kernel_launch(void* const* d_in, const int* in_sizes, int n_in,
                              void* d_out, int out_size) {
    const float* x   = (const float*)d_in[0];
    const int*   ei  = (const int*)d_in[1];
    const int*   eli = (const int*)d_in[2];
    const float* W1  = (const float*)d_in[3];
    const float* b1  = (const float*)d_in[4];
    const float* W2  = (const float*)d_in[5];
    const float* b2  = (const float*)d_in[6];
    const float* Wf1 = (const float*)d_in[7];
    const float* bf1 = (const float*)d_in[8];
    const float* Wf2 = (const float*)d_in[9];
    const float* bf2 = (const float*)d_in[10];
    float* out = (float*)d_out;

    const int n  = in_sizes[0] / DIN;
    const int ne = in_sizes[1] / 2;
    const int nq = in_sizes[2] / 2;

    const int PIPE_SMEM = (128 * 136 + 2 * 128 * 40) * 2;   // 55296 B
    cudaFuncSetAttribute(gemmfill_k, cudaFuncAttributeMaxDynamicSharedMemorySize, PIPE_SMEM);

    const int mb = (n + 127) / 128;                 // GEMM row tiles (391)
    const int nb = (n + 255) / 256;                 // scan blocks (196, <=256)
    const int aggBlocks = (n * 32 + 255) / 256;     // warp-per-node blocks
    const int nx4 = (n * DIN) / 4;
    const int wtot = DIN * DHID + DIN * DFCH + DHID * DOUT + DFCH * DOUT;
    const int nitems = nx4 + wtot;

    // 1. [prep (x->fp16, weights->fp16^T) || histogram]
    const int pgrp = (nitems + 767) / 768;
    prephist_k<<<4 * pgrp, 256>>>(x, W1, Wf1, W2, Wf2, ei + ne, nx4, nitems, ne);
    // 2. single-kernel scan -> rowptr, cursor, dinv (+ cnt reset)
    scanall_k<<<nb, 256>>>(nb, n);
    // 3. [F1 GEMM + H1 GEMM (dinv-scaled) || CSR fill]
    gemmfill_k<<<4 * mb, 256, PIPE_SMEM>>>(bf1, ei, ne, mb, n);
    // 4. agg1 -> A1 (pure, high occupancy)
    agg1_k<<<aggBlocks, 256>>>(b1, n);
    // 5. [H2' = dinv*(A1@W2) || FC = F1@Wf2+bf2]
    gemmh2fc_k<<<2 * mb, 256>>>(bf2, n, mb);
    // 6. z = 0.5*(agg(H2')+b2) + 0.5*FC
    agg2z_k<<<aggBlocks, 256>>>(b2, n);
    // 7. edge dot-product decode
    decodeh_k<<<(nq * 8 + 255) / 256, 256>>>(eli, out, nq);
}

// round 17
// speedup vs baseline: 1.4059x; 1.0293x over previous
#include <cuda_runtime.h>
#include <cuda_fp16.h>
#include <math.h>
#include <stdint.h>

// Problem constants (fixed by the dataset)
#define NN   50000
#define NE   1600000
#define DIN  128
#define DHID 128
#define DOUT 64
#define DFCH 256

// ---------------- scratch (device globals; no allocation allowed) ----------
static __device__ __align__(16) __half g_xh [NN * DIN];   // x, fp16
static __device__ __align__(16) __half g_H1h[NN * DHID];  // dinv * (x @ W1), fp16
static __device__ __align__(16) __half g_A1h[NN * DHID];  // relu(agg1 + b1), fp16
static __device__ __align__(16) __half g_H2h[NN * DOUT];  // dinv * (A1 @ W2), fp16
static __device__ __align__(16) __half g_F1h[NN * DFCH];  // relu(x@Wf1+bf1), fp16
static __device__ __align__(16) __half g_FCh[NN * DOUT];  // F1@Wf2+bf2, fp16
static __device__ __align__(16) __half g_Zh[NN * DOUT];   // 0.5*gcn + 0.5*fc, fp16
// fp16 transposed weights: Wt[n][k]
static __device__ __align__(16) __half g_W1t [DHID * DIN];
static __device__ __align__(16) __half g_Wf1t[DFCH * DIN];
static __device__ __align__(16) __half g_W2t [DOUT * DHID];
static __device__ __align__(16) __half g_Wf2t[DOUT * DFCH];
static __device__ int   g_cnt[NN];                        // zero at rest
static __device__ int   g_rowptr[NN + 1];
static __device__ int   g_cursor[NN];
static __device__ int   g_col[NE];
static __device__ float g_dinv[NN];
static __device__ int   g_bsum[256];
static __device__ int   g_tick;                           // zero at rest
static __device__ int   g_flag;                           // zero at rest
static __device__ int   g_done;                           // zero at rest

// ---------------- fused prep (x->fp16, weights->fp16^T) || histogram --------
__global__ void prephist_k(const float* __restrict__ x,
                           const float* __restrict__ W1, const float* __restrict__ Wf1,
                           const float* __restrict__ W2, const float* __restrict__ Wf2,
                           const int* __restrict__ dst,
                           int nx4, int nitems, int ne) {
    const int role = blockIdx.x & 3;
    const int grp  = blockIdx.x >> 2;
    if (role == 3) {                               // histogram chunk
        const int nch = gridDim.x >> 2;
        const int per = (ne + nch - 1) / nch;
        const int s = grp * per;
        const int e = min(s + per, ne);
        for (int i = s + (int)threadIdx.x; i < e; i += 256)
            atomicAdd(&g_cnt[dst[i]], 1);
        return;
    }
    const int p = grp * 3 + role;                  // prep block index
    int i = p * 256 + threadIdx.x;
    if (i >= nitems) return;
    if (i < nx4) {
        float4 v = *(const float4*)&x[(size_t)i * 4];
        uint2 u;
        *(__half2*)&u.x = __floats2half2_rn(v.x, v.y);
        *(__half2*)&u.y = __floats2half2_rn(v.z, v.w);
        *(uint2*)&g_xh[(size_t)i * 4] = u;
        return;
    }
    int j = i - nx4;
    if (j < DIN * DHID) {
        int nn = j / DIN, k = j % DIN;
        g_W1t[j] = __float2half(W1[k * DHID + nn]);
        return;
    }
    j -= DIN * DHID;
    if (j < DIN * DFCH) {
        int nn = j / DIN, k = j % DIN;
        g_Wf1t[j] = __float2half(Wf1[k * DFCH + nn]);
        return;
    }
    j -= DIN * DFCH;
    if (j < DHID * DOUT) {
        int nn = j / DHID, k = j % DHID;
        g_W2t[j] = __float2half(W2[k * DOUT + nn]);
        return;
    }
    j -= DHID * DOUT;
    if (j < DFCH * DOUT) {
        int nn = j / DFCH, k = j % DFCH;
        g_Wf2t[j] = __float2half(Wf2[k * DOUT + nn]);
    }
}

// ---------------- single-kernel scan (flag-spin handshake) -------------------
__global__ void scanall_k(int nbl, int n) {
    __shared__ int sm[256];
    __shared__ int lastBlk;
    const int t = threadIdx.x;
    const int i = blockIdx.x * 256 + t;
    const int v = (i < n) ? g_cnt[i] : 0;
    sm[t] = v;
    __syncthreads();
    for (int d = 1; d < 256; d <<= 1) {
        int a = (t >= d) ? sm[t - d] : 0;
        __syncthreads();
        sm[t] += a;
        __syncthreads();
    }
    const int incl = sm[t];
    if (t == 0) {
        g_bsum[blockIdx.x] = sm[255];
        __threadfence();
        lastBlk = (atomicAdd(&g_tick, 1) == nbl - 1);
    }
    __syncthreads();
    if (lastBlk) {
        __shared__ int sb[256];
        int bv = (t < nbl) ? g_bsum[t] : 0;
        sb[t] = bv;
        __syncthreads();
        for (int d = 1; d < 256; d <<= 1) {
            int a = (t >= d) ? sb[t - d] : 0;
            __syncthreads();
            sb[t] += a;
            __syncthreads();
        }
        if (t < nbl) g_bsum[t] = sb[t] - bv;     // exclusive
        if (t == 0) {
            g_rowptr[n] = sb[255];
            g_tick = 0;
            __threadfence();
            atomicExch(&g_flag, 1);
        }
        __syncthreads();
    }
    if (t == 0) {
        while (atomicAdd(&g_flag, 0) == 0) {}
    }
    __syncthreads();
    __threadfence();
    if (i < n) {
        int excl = g_bsum[blockIdx.x] + incl - v;
        g_rowptr[i] = excl;
        g_cursor[i] = excl;
        g_dinv[i]   = rsqrtf((float)(v + 1));
        g_cnt[i]    = 0;
    }
    __syncthreads();
    if (t == 0) {
        if (atomicAdd(&g_done, 1) == nbl - 1) {
            g_done = 0;
            g_flag = 0;
        }
    }
}

// ---------------- mma / cp.async / ldmatrix helpers --------------------------
__device__ __forceinline__ void mma_f16(float* d, const uint32_t* a, const uint32_t* b) {
    asm volatile(
        "mma.sync.aligned.m16n8k16.row.col.f32.f16.f16.f32 "
        "{%0,%1,%2,%3}, {%4,%5,%6,%7}, {%8,%9}, {%0,%1,%2,%3};"
        : "+f"(d[0]), "+f"(d[1]), "+f"(d[2]), "+f"(d[3])
        : "r"(a[0]), "r"(a[1]), "r"(a[2]), "r"(a[3]), "r"(b[0]), "r"(b[1]));
}

__device__ __forceinline__ void ldsm_x4(uint32_t& r0, uint32_t& r1,
                                        uint32_t& r2, uint32_t& r3, uint32_t addr) {
    asm volatile("ldmatrix.sync.aligned.m8n8.x4.shared.b16 {%0,%1,%2,%3}, [%4];"
                 : "=r"(r0), "=r"(r1), "=r"(r2), "=r"(r3) : "r"(addr));
}

__device__ __forceinline__ uint32_t smem_u32(const void* p) {
    return (uint32_t)__cvta_generic_to_shared(p);
}
__device__ __forceinline__ void cpa16(uint32_t dst, const void* src, int sz) {
    asm volatile("cp.async.cg.shared.global [%0], [%1], 16, %2;"
                 :: "r"(dst), "l"(src), "r"(sz));
}
__device__ __forceinline__ void cpa_commit() {
    asm volatile("cp.async.commit_group;");
}
template <int NP>
__device__ __forceinline__ void cpa_wait() {
    asm volatile("cp.async.wait_group %0;" :: "n"(NP));
}

// ------------ fp16 mma core over one 32-k stage (ldmatrix fragments) ---------
// As: [128][40] halves. Wts: [n][WT_STR] halves (k-contig rows).
// A frag: lanes 0-15 -> rows 0-15 @ kb, lanes 16-31 -> rows 0-15 @ kb+8
//   => matrices (r0..7,k)(r8..15,k)(r0..7,k+8)(r8..15,k+8) = mma a0,a1,a2,a3.
// B frag: lanes 0-7 (n,k), 8-15 (n,k+8), 16-23 (n+8,k), 24-31 (n+8,k+8)
//   => regs = b0(nt), b1(nt), b0(nt+1), b1(nt+1).
template <int NT, int WT_STR>
__device__ __forceinline__ void mma_stage16(const __half* As, const __half* Wts,
                                            int kglob, float acc[2][NT][4],
                                            int lane, int warpM, int warpN) {
    const uint32_t asb = smem_u32(As);
    const uint32_t wsb = smem_u32(Wts);
    const int rowA = warpM * 32 + (lane & 15);
    const int kA   = (lane >> 4) << 3;
    const int nB   = warpN * (NT * 8) + ((lane >> 4) << 3) + (lane & 7);
    const int kB   = ((lane >> 3) & 1) << 3;
#pragma unroll
    for (int kk = 0; kk < 2; kk++) {
        const int kb = kk * 16;
        uint32_t a[2][4];
#pragma unroll
        for (int mt = 0; mt < 2; mt++) {
            uint32_t addr = asb + (uint32_t)(((rowA + mt * 16) * 40) + kb + kA) * 2u;
            ldsm_x4(a[mt][0], a[mt][1], a[mt][2], a[mt][3], addr);
        }
#pragma unroll
        for (int ntp = 0; ntp < NT / 2; ntp++) {
            uint32_t addr = wsb + (uint32_t)(((nB + ntp * 16) * WT_STR)
                                             + kglob + kb + kB) * 2u;
            uint32_t b0, b1, b2, b3;
            ldsm_x4(b0, b1, b2, b3, addr);
            uint32_t q0[2] = {b0, b1};
            uint32_t q1[2] = {b2, b3};
            mma_f16(acc[0][ntp * 2],     a[0], q0);
            mma_f16(acc[1][ntp * 2],     a[1], q0);
            mma_f16(acc[0][ntp * 2 + 1], a[0], q1);
            mma_f16(acc[1][ntp * 2 + 1], a[1], q1);
        }
    }
}

// ------------ epilogue: bias/relu/dinv-scale, fp16 store --------------------
template <int N, int NT, bool BIAS, bool RELU, bool SCALE>
__device__ __forceinline__ void gemm_epi(float acc[2][NT][4],
                                         const float* __restrict__ bias,
                                         __half* __restrict__ C, int nRows,
                                         int rowBase, int colBase,
                                         int lane, int warpM, int warpN) {
#pragma unroll
    for (int mt = 0; mt < 2; mt++) {
#pragma unroll
        for (int half = 0; half < 2; half++) {
            int row = rowBase + warpM * 32 + mt * 16 + (lane >> 2) + half * 8;
            if (row >= nRows) continue;
            float dsc = SCALE ? g_dinv[row] : 1.f;
#pragma unroll
            for (int nt = 0; nt < NT; nt++) {
                int col = colBase + warpN * (NT * 8) + nt * 8 + (lane & 3) * 2;
                float v0 = acc[mt][nt][half * 2 + 0];
                float v1 = acc[mt][nt][half * 2 + 1];
                if (BIAS) { v0 += bias[col]; v1 += bias[col + 1]; }
                if (RELU) { v0 = fmaxf(v0, 0.f); v1 = fmaxf(v1, 0.f); }
                if (SCALE) { v0 *= dsc; v1 *= dsc; }
                *(__half2*)&C[(size_t)row * N + col] = __floats2half2_rn(v0, v1);
            }
        }
    }
}

// ------------ pipelined fp16 GEMM (BN=128, Wt smem-resident, A cp.async) ----
template <int K, int N, bool BIAS, bool RELU, bool SCALE>
__device__ __forceinline__ void gemm16_pipe(const __half* __restrict__ A,
                                            const __half* __restrict__ Wt, // [N][K]
                                            const float* __restrict__ bias,
                                            __half* __restrict__ C, int nRows,
                                            int tileM, int colBase, char* smraw) {
    constexpr int BN = 128, NT = 8;
    constexpr int WT_STR = K + 8;
    __half* Wts = (__half*)smraw;
    __half* As0 = Wts + BN * WT_STR;
    __half* As1 = As0 + 128 * 40;
    __half* Asb[2] = {As0, As1};

    const int tid = threadIdx.x;
    const int lane = tid & 31;
    const int wid = tid >> 5;
    const int warpM = wid & 3;
    const int warpN = wid >> 2;
    const int rowBase = tileM * 128;

#pragma unroll
    for (int i = 0; i < BN * K / 8 / 256; i++) {
        int s = tid + i * 256;
        int row = s / (K / 8), c8 = s % (K / 8);
        cpa16(smem_u32(&Wts[row * WT_STR + c8 * 8]),
              &Wt[(size_t)(colBase + row) * K + c8 * 8], 16);
    }
    auto loadA = [&](int st, int k0) {
#pragma unroll
        for (int i = 0; i < 2; i++) {
            int s = tid + i * 256;
            int row = s >> 2, c8 = s & 3;
            int grow = rowBase + row;
            int ok = grow < nRows;
            cpa16(smem_u32(&Asb[st][row * 40 + c8 * 8]),
                  &A[(size_t)(ok ? grow : 0) * K + k0 + c8 * 8], ok ? 16 : 0);
        }
        cpa_commit();
    };

    float acc[2][NT][4];
#pragma unroll
    for (int mt = 0; mt < 2; mt++)
#pragma unroll
        for (int nt = 0; nt < NT; nt++)
#pragma unroll
            for (int i = 0; i < 4; i++) acc[mt][nt][i] = 0.f;

    loadA(0, 0);
    constexpr int NST = K / 32;
#pragma unroll
    for (int it = 0; it < NST; it++) {
        int st = it & 1;
        if (it + 1 < NST) loadA(st ^ 1, (it + 1) * 32);
        if (it + 1 < NST) cpa_wait<1>(); else cpa_wait<0>();
        __syncthreads();
        mma_stage16<NT, WT_STR>(Asb[st], Wts, it * 32, acc, lane, warpM, warpN);
        __syncthreads();
    }
    gemm_epi<N, NT, BIAS, RELU, SCALE>(acc, bias, C, nRows, rowBase, colBase,
                                       lane, warpM, warpN);
}

// ------------ synchronous fp16 GEMM (BN=64, per-stage loads) ----------------
template <int K, int N, bool BIAS, bool RELU, bool SCALE>
__device__ __forceinline__ void gemm16_sync(const __half* __restrict__ A,
                                            const __half* __restrict__ Wt, // [N][K]
                                            const float* __restrict__ bias,
                                            __half* __restrict__ C, int nRows,
                                            int tileM, __half* As, __half* Ws) {
    constexpr int NT = 4;
    const int tid = threadIdx.x;
    const int lane = tid & 31;
    const int wid = tid >> 5;
    const int warpM = wid & 3;
    const int warpN = wid >> 2;
    const int rowBase = tileM * 128;

    float acc[2][NT][4];
#pragma unroll
    for (int mt = 0; mt < 2; mt++)
#pragma unroll
        for (int nt = 0; nt < NT; nt++)
#pragma unroll
            for (int i = 0; i < 4; i++) acc[mt][nt][i] = 0.f;

    for (int k0 = 0; k0 < K; k0 += 32) {
#pragma unroll
        for (int i = 0; i < 2; i++) {
            int s = tid + i * 256;
            int row = s >> 2, c8 = s & 3;
            int grow = rowBase + row;
            uint4 v = make_uint4(0u, 0u, 0u, 0u);
            if (grow < nRows) v = *(const uint4*)&A[(size_t)grow * K + k0 + c8 * 8];
            *(uint4*)&As[row * 40 + c8 * 8] = v;
        }
        {
            int row = tid >> 2, c8 = tid & 3;
            *(uint4*)&Ws[row * 40 + c8 * 8] =
                *(const uint4*)&Wt[(size_t)row * K + k0 + c8 * 8];
        }
        __syncthreads();
        mma_stage16<NT, 40>(As, Ws, 0, acc, lane, warpM, warpN);
        __syncthreads();
    }
    gemm_epi<N, NT, BIAS, RELU, SCALE>(acc, bias, C, nRows, rowBase, 0,
                                       lane, warpM, warpN);
}

// ---------------- aggregation node body --------------------------------------
// H PRESCALED by dinv. Gather-sum with coalesced 32-index batches distributed
// via shuffle (1 LDG per 32 edges instead of 32 broadcast LDGs), and fp16
// pairwise HADD2 tree before fp32 accumulation.
template <int F, bool RELU, bool COMBINE>
__device__ __forceinline__ void agg_node(int gw, const __half* __restrict__ H,
                                         const float* __restrict__ bias,
                                         const __half* __restrict__ FCh,
                                         __half* __restrict__ Out) {
    const int lane = threadIdx.x & 31;
    constexpr int FPT = F / 32;
    const int colb = lane * FPT;
    const float di = g_dinv[gw];

    float acc[FPT];
    if constexpr (FPT == 4) {
        uint2 u = *(const uint2*)&H[(size_t)gw * F + colb];
        float2 p0 = __half22float2(*(const __half2*)&u.x);
        float2 p1 = __half22float2(*(const __half2*)&u.y);
        acc[0] = p0.x; acc[1] = p0.y; acc[2] = p1.x; acc[3] = p1.y;
    } else {
        uint32_t u = *(const uint32_t*)&H[(size_t)gw * F + colb];
        float2 p = __half22float2(*(const __half2*)&u);
        acc[0] = p.x; acc[1] = p.y;
    }

    int e = g_rowptr[gw];
    const int end = g_rowptr[gw + 1];
    while (e < end) {
        const int cnt = min(end - e, 32);
        int myIdx = 0;
        if (lane < cnt) myIdx = __ldg(&g_col[e + lane]);
        int j = 0;
        for (; j + 3 < cnt; j += 4) {
            int s0 = __shfl_sync(0xffffffffu, myIdx, j + 0);
            int s1 = __shfl_sync(0xffffffffu, myIdx, j + 1);
            int s2 = __shfl_sync(0xffffffffu, myIdx, j + 2);
            int s3 = __shfl_sync(0xffffffffu, myIdx, j + 3);
            if constexpr (FPT == 4) {
                uint2 u0 = *(const uint2*)&H[(size_t)s0 * F + colb];
                uint2 u1 = *(const uint2*)&H[(size_t)s1 * F + colb];
                uint2 u2 = *(const uint2*)&H[(size_t)s2 * F + colb];
                uint2 u3 = *(const uint2*)&H[(size_t)s3 * F + colb];
                __half2 t0 = __hadd2(*(const __half2*)&u0.x, *(const __half2*)&u1.x);
                __half2 t1 = __hadd2(*(const __half2*)&u0.y, *(const __half2*)&u1.y);
                __half2 t2 = __hadd2(*(const __half2*)&u2.x, *(const __half2*)&u3.x);
                __half2 t3 = __hadd2(*(const __half2*)&u2.y, *(const __half2*)&u3.y);
                float2 f0 = __half22float2(t0);
                float2 f1 = __half22float2(t1);
                float2 f2 = __half22float2(t2);
                float2 f3 = __half22float2(t3);
                acc[0] += f0.x + f2.x;
                acc[1] += f0.y + f2.y;
                acc[2] += f1.x + f3.x;
                acc[3] += f1.y + f3.y;
            } else {
                uint32_t u0 = *(const uint32_t*)&H[(size_t)s0 * F + colb];
                uint32_t u1 = *(const uint32_t*)&H[(size_t)s1 * F + colb];
                uint32_t u2 = *(const uint32_t*)&H[(size_t)s2 * F + colb];
                uint32_t u3 = *(const uint32_t*)&H[(size_t)s3 * F + colb];
                __half2 t01 = __hadd2(*(const __half2*)&u0, *(const __half2*)&u1);
                __half2 t23 = __hadd2(*(const __half2*)&u2, *(const __half2*)&u3);
                float2 f01 = __half22float2(t01);
                float2 f23 = __half22float2(t23);
                acc[0] += f01.x + f23.x;
                acc[1] += f01.y + f23.y;
            }
        }
        for (; j + 1 < cnt; j += 2) {
            int s0 = __shfl_sync(0xffffffffu, myIdx, j + 0);
            int s1 = __shfl_sync(0xffffffffu, myIdx, j + 1);
            if constexpr (FPT == 4) {
                uint2 u0 = *(const uint2*)&H[(size_t)s0 * F + colb];
                uint2 u1 = *(const uint2*)&H[(size_t)s1 * F + colb];
                __half2 t0 = __hadd2(*(const __half2*)&u0.x, *(const __half2*)&u1.x);
                __half2 t1 = __hadd2(*(const __half2*)&u0.y, *(const __half2*)&u1.y);
                float2 f0 = __half22float2(t0);
                float2 f1 = __half22float2(t1);
                acc[0] += f0.x; acc[1] += f0.y;
                acc[2] += f1.x; acc[3] += f1.y;
            } else {
                uint32_t u0 = *(const uint32_t*)&H[(size_t)s0 * F + colb];
                uint32_t u1 = *(const uint32_t*)&H[(size_t)s1 * F + colb];
                __half2 t01 = __hadd2(*(const __half2*)&u0, *(const __half2*)&u1);
                float2 f01 = __half22float2(t01);
                acc[0] += f01.x; acc[1] += f01.y;
            }
        }
        if (j < cnt) {
            int s0 = __shfl_sync(0xffffffffu, myIdx, j);
            if constexpr (FPT == 4) {
                uint2 u0 = *(const uint2*)&H[(size_t)s0 * F + colb];
                float2 a0 = __half22float2(*(const __half2*)&u0.x);
                float2 a1 = __half22float2(*(const __half2*)&u0.y);
                acc[0] += a0.x; acc[1] += a0.y;
                acc[2] += a1.x; acc[3] += a1.y;
            } else {
                uint32_t u0 = *(const uint32_t*)&H[(size_t)s0 * F + colb];
                float2 a = __half22float2(*(const __half2*)&u0);
                acc[0] += a.x; acc[1] += a.y;
            }
        }
        e += cnt;
    }

    float fc[FPT];
    if constexpr (COMBINE) {
        if constexpr (FPT == 2) {
            float2 f = __half22float2(*(const __half2*)&FCh[(size_t)gw * F + colb]);
            fc[0] = f.x; fc[1] = f.y;
        } else {
            uint2 u = *(const uint2*)&FCh[(size_t)gw * F + colb];
            float2 f0 = __half22float2(*(const __half2*)&u.x);
            float2 f1 = __half22float2(*(const __half2*)&u.y);
            fc[0] = f0.x; fc[1] = f0.y; fc[2] = f1.x; fc[3] = f1.y;
        }
    }

#pragma unroll
    for (int j = 0; j < FPT; j++) {
        float o = di * acc[j] + bias[colb + j];
        if (RELU) o = fmaxf(o, 0.f);
        if (COMBINE) o = 0.5f * o + 0.5f * fc[j];
        acc[j] = o;
    }
    if constexpr (FPT == 4) {
        uint2 u;
        *(__half2*)&u.x = __floats2half2_rn(acc[0], acc[1]);
        *(__half2*)&u.y = __floats2half2_rn(acc[2], acc[3]);
        *(uint2*)&Out[(size_t)gw * F + colb] = u;
    } else {
        *(__half2*)&Out[(size_t)gw * F + colb] = __floats2half2_rn(acc[0], acc[1]);
    }
}

// ---- fused: F1 + H1 GEMM tiles (3 of 4 blocks) || CSR-fill (1 of 4) --------
__global__ void __launch_bounds__(256, 2) gemmfill_k(const float* __restrict__ bf1,
                                                     const int* __restrict__ ei,
                                                     int ne, int mb, int n) {
    extern __shared__ char dyn_sm[];
    const int role = blockIdx.x & 3;
    const int grp  = blockIdx.x >> 2;
    if (role == 3) {                               // fill chunk
        const int nch = gridDim.x >> 2;
        const int per = (ne + nch - 1) / nch;
        const int s = grp * per;
        const int e = min(s + per, ne);
        for (int i = s + (int)threadIdx.x; i < e; i += 256) {
            int sv = ei[i];
            int dv = ei[ne + i];
            g_col[atomicAdd(&g_cursor[dv], 1)] = sv;
        }
        return;
    }
    const int idx = grp * 3 + role;                // 0 .. 3*mb-1
    if (idx < 2 * mb) {
        gemm16_pipe<DIN, DFCH, true, true, false>(g_xh, g_Wf1t, bf1, g_F1h, n,
                                                  idx % mb, (idx / mb) * 128, dyn_sm);
    } else {
        gemm16_pipe<DIN, DHID, false, false, true>(g_xh, g_W1t, nullptr, g_H1h, n,
                                                   idx - 2 * mb, 0, dyn_sm);
    }
}

// ---- pure agg1 (no smem, low regs -> high occupancy) ------------------------
__global__ void __launch_bounds__(256) agg1_k(const float* __restrict__ b1, int n) {
    const int gw = (blockIdx.x * 256 + threadIdx.x) >> 5;
    if (gw >= n) return;
    agg_node<DHID, true, false>(gw, g_H1h, b1, nullptr, g_A1h);
}

// ---- striped: H2' = dinv*(A1@W2) (even) || FC = F1@Wf2+bf2 (odd) -----------
__global__ void __launch_bounds__(256) gemmh2fc_k(const float* __restrict__ bf2,
                                                  int n, int mb) {
    __shared__ __half smem[128 * 40 + 64 * 40];
    const int role = blockIdx.x & 1;
    const int tile = blockIdx.x >> 1;
    if (tile >= mb) return;
    if (role == 0) {
        gemm16_sync<DHID, DOUT, false, false, true>(g_A1h, g_W2t, nullptr, g_H2h, n,
                                                    tile, smem, smem + 128 * 40);
    } else {
        gemm16_sync<DFCH, DOUT, true, false, false>(g_F1h, g_Wf2t, bf2, g_FCh, n,
                                                    tile, smem, smem + 128 * 40);
    }
}

// ---- agg2 + combine: z = 0.5*(agg(H2')+b2) + 0.5*FC -------------------------
__global__ void __launch_bounds__(256) agg2z_k(const float* __restrict__ b2, int n) {
    const int gw = (blockIdx.x * 256 + threadIdx.x) >> 5;
    if (gw >= n) return;
    agg_node<DOUT, false, true>(gw, g_H2h, b2, g_FCh, g_Zh);
}

// ---------------- decode (fp16 z): 8 lanes/query, uint4 loads ---------------
__global__ void __launch_bounds__(256) decodeh_k(const int* __restrict__ eli,
                                                 float* __restrict__ out, int nq) {
    int t = blockIdx.x * 256 + threadIdx.x;
    int q = t >> 3;
    int l = t & 7;
    if (q >= nq) return;
    int a = eli[q];
    int b = eli[nq + q];
    uint4 ua = *(const uint4*)&g_Zh[(size_t)a * DOUT + l * 8];
    uint4 ub = *(const uint4*)&g_Zh[(size_t)b * DOUT + l * 8];
    float2 a0 = __half22float2(*(const __half2*)&ua.x);
    float2 a1 = __half22float2(*(const __half2*)&ua.y);
    float2 a2 = __half22float2(*(const __half2*)&ua.z);
    float2 a3 = __half22float2(*(const __half2*)&ua.w);
    float2 b0 = __half22float2(*(const __half2*)&ub.x);
    float2 b1 = __half22float2(*(const __half2*)&ub.y);
    float2 b2 = __half22float2(*(const __half2*)&ub.z);
    float2 b3 = __half22float2(*(const __half2*)&ub.w);
    float p = a0.x * b0.x + a0.y * b0.y + a1.x * b1.x + a1.y * b1.y
            + a2.x * b2.x + a2.y * b2.y + a3.x * b3.x + a3.y * b3.y;
    p += __shfl_xor_sync(0xffffffffu, p, 4);
    p += __shfl_xor_sync(0xffffffffu, p, 2);
    p += __shfl_xor_sync(0xffffffffu, p, 1);
    if (l == 0) out[q] = p;
}

// ---------------- launch ----------------------------------------------------
extern "C" void kernel_launch(void* const* d_in, const int* in_sizes, int n_in,
                              void* d_out, int out_size) {
    const float* x   = (const float*)d_in[0];
    const int*   ei  = (const int*)d_in[1];
    const int*   eli = (const int*)d_in[2];
    const float* W1  = (const float*)d_in[3];
    const float* b1  = (const float*)d_in[4];
    const float* W2  = (const float*)d_in[5];
    const float* b2  = (const float*)d_in[6];
    const float* Wf1 = (const float*)d_in[7];
    const float* bf1 = (const float*)d_in[8];
    const float* Wf2 = (const float*)d_in[9];
    const float* bf2 = (const float*)d_in[10];
    float* out = (float*)d_out;

    const int n  = in_sizes[0] / DIN;
    const int ne = in_sizes[1] / 2;
    const int nq = in_sizes[2] / 2;

    const int PIPE_SMEM = (128 * 136 + 2 * 128 * 40) * 2;   // 55296 B
    cudaFuncSetAttribute(gemmfill_k, cudaFuncAttributeMaxDynamicSharedMemorySize, PIPE_SMEM);

    const int mb = (n + 127) / 128;                 // GEMM row tiles (391)
    const int nb = (n + 255) / 256;                 // scan blocks (196, <=256)
    const int aggBlocks = (n * 32 + 255) / 256;     // warp-per-node blocks
    const int nx4 = (n * DIN) / 4;
    const int wtot = DIN * DHID + DIN * DFCH + DHID * DOUT + DFCH * DOUT;
    const int nitems = nx4 + wtot;

    // 1. [prep (x->fp16, weights->fp16^T) || histogram]
    const int pgrp = (nitems + 767) / 768;
    prephist_k<<<4 * pgrp, 256>>>(x, W1, Wf1, W2, Wf2, ei + ne, nx4, nitems, ne);
    // 2. single-kernel scan -> rowptr, cursor, dinv (+ cnt reset)
    scanall_k<<<nb, 256>>>(nb, n);
    // 3. [F1 GEMM + H1 GEMM (dinv-scaled) || CSR fill]
    gemmfill_k<<<4 * mb, 256, PIPE_SMEM>>>(bf1, ei, ne, mb, n);
    // 4. agg1 -> A1 (pure, high occupancy)
    agg1_k<<<aggBlocks, 256>>>(b1, n);
    // 5. [H2' = dinv*(A1@W2) || FC = F1@Wf2+bf2]
    gemmh2fc_k<<<2 * mb, 256>>>(bf2, n, mb);
    // 6. z = 0.5*(agg(H2')+b2) + 0.5*FC
    agg2z_k<<<aggBlocks, 256>>>(b2, n);
    // 7. edge dot-product decode
    decodeh_k<<<(nq * 8 + 255) / 256, 256>>>(eli, out, nq);
}